// round 12
// baseline (speedup 1.0000x reference)
#include <cuda_runtime.h>
#include <cuda_bf16.h>
#include <math.h>
#include <stdint.h>

// ---------------------------------------------------------------------------
// Problem constants: x(2,4,1024,1024), HEADS=8, D=128, ROT_DIM=64
// ---------------------------------------------------------------------------
#define BATCH   2
#define CH      4
#define BC      (BATCH*CH)        // 8
#define NB      1024              // BINS
#define NH      8                 // heads
#define HD      128               // head dim
#define BCN     (BC*NH)           // 64
#define ROT     64                // rotary dims

// Scratch (static __device__ — no allocations allowed)
__device__ float g_y [BC  * NB * NB];   // proj gemm out (pre-conv)      32MB
__device__ float g_p [BC  * NB * NB];   // conv+bias out (tf32, also V^T) 32MB
__device__ float g_q [BCN * NB * HD];   // roped Q (= K), tf32            32MB
__device__ float g_s [BCN * NB * NB];   // attention probs, tf32         256MB
__device__ float g_av[BCN * NB * HD];   // softmax @ V                    32MB
__device__ float g_am[BC  * NB * NB];   // merged heads, tf32             32MB
__device__ float g_xc[BC  * NB * NB];   // x converted to tf32            32MB
__device__ float g_wl[CH  * NB * NB];   // w_lin tf32                     16MB
__device__ float g_wo[CH  * NB * NB];   // w_out tf32                     16MB

// ---------------------------------------------------------------------------
// helpers
// ---------------------------------------------------------------------------
__device__ __forceinline__ unsigned f2tf32(float x) {
    unsigned r;
    asm("cvt.rna.tf32.f32 %0, %1;" : "=r"(r) : "f"(x));
    return r;
}
__device__ __forceinline__ float rtf(float x) { return __uint_as_float(f2tf32(x)); }

__device__ __forceinline__ uint32_t smem_u32(const void* p) {
    uint32_t a;
    asm("{ .reg .u64 t; cvta.to.shared.u64 t, %1; cvt.u32.u64 %0, t; }"
        : "=r"(a) : "l"(p));
    return a;
}

__device__ __forceinline__ void cp16(uint32_t dst, const void* src) {
    asm volatile("cp.async.ca.shared.global [%0], [%1], 16;" :: "r"(dst), "l"(src));
}

// cp.async arrive-on-mbarrier, NOINC (plain form is inc-then-arrive -> deadlock)
__device__ __forceinline__ void cp_arrive(uint32_t mbar) {
    asm volatile("cp.async.mbarrier.arrive.noinc.shared.b64 [%0];" :: "r"(mbar) : "memory");
}

#define MBAR_INIT(addr, cnt) \
    asm volatile("mbarrier.init.shared.b64 [%0], %1;" :: "r"(addr), "r"(cnt) : "memory")

__device__ __forceinline__ void mbar_arrive(uint32_t addr) {
    asm volatile("mbarrier.arrive.shared.b64 _, [%0];" :: "r"(addr) : "memory");
}

__device__ __forceinline__ void mbar_wait(uint32_t addr, uint32_t parity) {
    asm volatile(
        "{\n\t.reg .pred P1;\n\t"
        "WL_%=:\n\t"
        "mbarrier.try_wait.parity.acquire.cta.shared::cta.b64 P1, [%0], %1, 0x989680;\n\t"
        "@P1 bra.uni WD_%=;\n\t"
        "bra.uni WL_%=;\n\t"
        "WD_%=:\n\t}"
        :: "r"(addr), "r"(parity) : "memory");
}

// ldmatrix x4: 4 m8n8 b16 tiles; tf32 data: lane i of each tile gets fp32
// element [i/4][i%4] -> exactly the m16n8k8 tf32 mma fragment layout.
__device__ __forceinline__ void ldsm4(unsigned& r0, unsigned& r1, unsigned& r2,
                                      unsigned& r3, uint32_t addr) {
    asm volatile("ldmatrix.sync.aligned.m8n8.x4.shared.b16 {%0,%1,%2,%3}, [%4];"
                 : "=r"(r0), "=r"(r1), "=r"(r2), "=r"(r3) : "r"(addr));
}

__device__ __forceinline__ void mma_tf32(float* d, const unsigned* a, const unsigned* b) {
    asm volatile(
        "mma.sync.aligned.m16n8k8.row.col.f32.tf32.tf32.f32 "
        "{%0,%1,%2,%3}, {%4,%5,%6,%7}, {%8,%9}, {%0,%1,%2,%3};"
        : "+f"(d[0]), "+f"(d[1]), "+f"(d[2]), "+f"(d[3])
        : "r"(a[0]), "r"(a[1]), "r"(a[2]), "r"(a[3]), "r"(b[0]), "r"(b[1]));
}

// ---------------------------------------------------------------------------
// elementwise tf32 rounding pass (for x, w_lin, w_out)
// ---------------------------------------------------------------------------
__global__ __launch_bounds__(256)
void cvt_tf32(const float* __restrict__ in, float* __restrict__ out, int n4)
{
    int i = blockIdx.x * 256 + threadIdx.x;
    if (i >= n4) return;
    float4 v = ((const float4*)in)[i];
    v.x = rtf(v.x); v.y = rtf(v.y); v.z = rtf(v.z); v.w = rtf(v.w);
    ((float4*)out)[i] = v;
}

// ---------------------------------------------------------------------------
// Batched NT GEMM, tensor cores (tf32, fp32 acc), inputs pre-rounded to tf32.
//   C[m,n] = sum_k A[m*lda+k] * B[n*ldb+k]
// 128 threads (4 warps, 2x2), block 128x128, warp tile 64x64 (4x8 m16n8k8):
// 128 B of smem per MMA (vs 187 at 64x32) -> crossbar-bound tensor% rises.
// BK=16, 4 smem slots, per-stage mbarrier pipeline (warps skew freely; the
// R5 lockstep failure does not apply). Frags via ldmatrix.x4.
// full[s]: 128 cp.async-noinc arrivals; empty[s]: 4 warp arrivals.
// __launch_bounds__(128,2): 2 CTAs/SM (regs ~190 < 256; smem 2x80KB).
// sym!=0 => C symmetric: CTAs with bn<bm exit; off-diag tiles mirror-store.
// ---------------------------------------------------------------------------
#define STG_F 5120          // floats per stage (2*128*20)
#define NSTG  4
#define GEMM_SMEM (64 + NSTG * STG_F * 4)   // 64B barriers + 80KB stages

__device__ __forceinline__ void issue_stage(uint32_t dbase, int slot,
    const float* Ag, const float* Bg, int kbase, int lda, int ldb, int tid)
{
    // 128 threads: thread r loads full 16-float rows of A and B
    uint32_t a_off = dbase + (uint32_t)(slot * STG_F + tid * 20) * 4u;
    uint32_t b_off = a_off + 2560u * 4u;
    const float* ap = Ag + (long)tid * lda + kbase;
    const float* bp = Bg + (long)tid * ldb + kbase;
    #pragma unroll
    for (int i = 0; i < 4; i++) {
        cp16(a_off + i * 16, ap + i * 4);
        cp16(b_off + i * 16, bp + i * 4);
    }
}

__global__ __launch_bounds__(128, 2)
void gemm_tc(const float* __restrict__ A, const float* __restrict__ B,
             float* __restrict__ C,
             int K, int lda, int ldb, int ldc,
             long sA, long sB, long sC, int modB, int sym)
{
    const int bm = blockIdx.y * 128;
    const int bn = blockIdx.x * 128;
    if (sym && bn < bm) return;          // symmetric: upper triangle only

    extern __shared__ float sm[];
    const uint32_t sbase = smem_u32(sm);     // barriers: full[4] @0, empty[4] @32
    const uint32_t dbase = sbase + 64;       // stage data

    const int tid = threadIdx.x;
    const int batch = blockIdx.z;

    const float* Ag = A + (long)batch * sA + (long)bm * lda;
    const float* Bg = B + (long)(batch % modB) * sB + (long)bn * ldb;
    C += (long)batch * sC;

    const int wid  = tid >> 5;
    const int lane = tid & 31;
    const int wm = wid & 1;             // 0..1 (64 rows)
    const int wn = wid >> 1;            // 0..1 (64 cols)
    const int g = lane >> 2;            // 0..7
    const int t = lane & 3;             // 0..3

    // ldmatrix per-lane address components
    const int a_ro = (lane & 7) + ((lane >> 3) & 1) * 8;   // 0..15
    const int a_co = (lane >> 4) * 4;                      // 0 or 4
    const int b_ro = (lane & 7) + (lane >> 4) * 8;         // 0..15
    const int b_co = ((lane >> 3) & 1) * 4;                // 0 or 4

    float acc[4][8][4];
    #pragma unroll
    for (int i = 0; i < 4; i++)
        #pragma unroll
        for (int j = 0; j < 8; j++)
            #pragma unroll
            for (int r = 0; r < 4; r++) acc[i][j][r] = 0.f;

    const int iters = K >> 4;           // BK = 16

    if (tid < NSTG) {
        MBAR_INIT(sbase + tid * 8, 128);        // full[tid]: all threads' cp.asyncs
        MBAR_INIT(sbase + 32 + tid * 8, 4);     // empty[tid]: one arrive per warp
    }
    __syncthreads();

    // prefill stages 0..2
    #pragma unroll
    for (int s = 0; s < 3; s++) {
        issue_stage(dbase, s, Ag, Bg, s * 16, lda, ldb, tid);
        cp_arrive(sbase + s * 8);
    }

    for (int it = 0; it < iters; ++it) {
        // 1) produce stage it+3
        const int pn = it + 3;
        if (pn < iters) {
            const int ps = pn & 3;
            if (pn >= NSTG)
                mbar_wait(sbase + 32 + ps * 8, ((pn >> 2) - 1) & 1);
            issue_stage(dbase, ps, Ag, Bg, pn * 16, lda, ldb, tid);
            cp_arrive(sbase + ps * 8);
        }

        // 2) wait for stage it
        const int slot = it & 3;
        mbar_wait(sbase + slot * 8, (it >> 2) & 1);

        const uint32_t aBase = dbase + (uint32_t)(slot * STG_F) * 4u;   // A [128][20]
        const uint32_t bBase = aBase + 2560u * 4u;                      // B [128][20]

        // 3) compute: 2 k-steps, warp tile 64x64, frags via ldmatrix.x4
        #pragma unroll
        for (int ks = 0; ks < 2; ++ks) {
            const int k0 = ks * 8;
            unsigned af[4][4], bf[8][2];
            #pragma unroll
            for (int mt = 0; mt < 4; mt++) {
                uint32_t addr = aBase +
                    (uint32_t)(((wm * 64 + mt * 16 + a_ro) * 20) + k0 + a_co) * 4u;
                ldsm4(af[mt][0], af[mt][1], af[mt][2], af[mt][3], addr);
            }
            #pragma unroll
            for (int np = 0; np < 4; np++) {
                uint32_t addr = bBase +
                    (uint32_t)(((wn * 64 + np * 16 + b_ro) * 20) + k0 + b_co) * 4u;
                ldsm4(bf[2*np][0], bf[2*np][1], bf[2*np+1][0], bf[2*np+1][1], addr);
            }
            #pragma unroll
            for (int mt = 0; mt < 4; mt++)
                #pragma unroll
                for (int nt = 0; nt < 8; nt++)
                    mma_tf32(acc[mt][nt], af[mt], bf[nt]);
        }

        // 4) stage consumed -> warp-level release (lane 0; warp converged)
        if (lane == 0) mbar_arrive(sbase + 32 + slot * 8);
    }

    // epilogue
    #pragma unroll
    for (int mt = 0; mt < 4; mt++) {
        const int row = bm + wm * 64 + mt * 16 + g;
        #pragma unroll
        for (int nt = 0; nt < 8; nt++) {
            const int col = bn + wn * 64 + nt * 8 + 2 * t;
            float2 v0 = make_float2(acc[mt][nt][0], acc[mt][nt][1]);
            float2 v1 = make_float2(acc[mt][nt][2], acc[mt][nt][3]);
            *(float2*)(C + (long)row * ldc + col)       = v0;
            *(float2*)(C + (long)(row + 8) * ldc + col) = v1;
        }
    }
    if (sym && bm != bn) {
        // mirror tile: S[col][row] = S[row][col]
        #pragma unroll
        for (int mt = 0; mt < 4; mt++) {
            const int row = bm + wm * 64 + mt * 16 + g;
            #pragma unroll
            for (int nt = 0; nt < 8; nt++) {
                const int col = bn + wn * 64 + nt * 8 + 2 * t;
                C[(long)col * ldc + row]           = acc[mt][nt][0];
                C[(long)(col + 1) * ldc + row]     = acc[mt][nt][1];
                C[(long)col * ldc + row + 8]       = acc[mt][nt][2];
                C[(long)(col + 1) * ldc + row + 8] = acc[mt][nt][3];
            }
        }
    }
}

// ---------------------------------------------------------------------------
// Depthwise conv (kernel 3, pad 1 along last axis) + bias; output tf32-rounded
// ---------------------------------------------------------------------------
__global__ __launch_bounds__(256)
void conv_bias(const float* __restrict__ y, const float* __restrict__ wc,
               const float* __restrict__ bias, float* __restrict__ p)
{
    long idx = (long)blockIdx.x * blockDim.x + threadIdx.x;   // 8M elems
    if (idx >= (long)BC * NB * NB) return;
    int o = (int)(idx & (NB - 1));
    int c = (int)((idx >> 20) & 3);
    float w0 = wc[c*3+0], w1 = wc[c*3+1], w2 = wc[c*3+2];
    float mid = y[idx];
    float lft = (o > 0)      ? y[idx - 1] : 0.f;
    float rgt = (o < NB - 1) ? y[idx + 1] : 0.f;
    p[idx] = rtf(fmaf(lft, w0, fmaf(mid, w1, fmaf(rgt, w2, bias[c]))));
}

// ---------------------------------------------------------------------------
// RoPE + transpose: Q[bcn][s][d] from p[bc][n*128+d][s]; output tf32-rounded
// ---------------------------------------------------------------------------
__global__ __launch_bounds__(256)
void rope_build(const float* __restrict__ p, float* __restrict__ Q)
{
    long idx = (long)blockIdx.x * blockDim.x + threadIdx.x;   // 4M
    if (idx >= (long)BCN * 64 * NB) return;
    int s   = (int)(idx & (NB - 1));
    int j   = (int)((idx >> 10) & 63);
    int bcn = (int)(idx >> 16);
    int bc = bcn >> 3, n = bcn & 7;

    const float* src = p + ((long)bc * NB + n * HD) * NB + s;
    float*       dst = Q + (long)bcn * (NB * HD) + (long)s * HD;

    if (j < 32) {
        float t0 = src[(2*j + 0) * NB];
        float t1 = src[(2*j + 1) * NB];
        float invf = powf(10000.f, -(float)(2*j) / (float)ROT);
        float ang = (float)s * invf;
        float cs = cosf(ang), sn = sinf(ang);
        dst[2*j + 0] = rtf(t0 * cs - t1 * sn);
        dst[2*j + 1] = rtf(t1 * cs + t0 * sn);
    } else {
        int d = ROT + (j - 32) * 2;
        dst[d + 0] = src[(d + 0) * NB];
        dst[d + 1] = src[(d + 1) * NB];
    }
}

// ---------------------------------------------------------------------------
// Row softmax with scale (one block per row of 1024); output tf32-rounded
// ---------------------------------------------------------------------------
__global__ __launch_bounds__(256)
void softmax_rows(float* __restrict__ S, float scale)
{
    float* row = S + (long)blockIdx.x * NB;
    const int t = threadIdx.x;
    __shared__ float red[32];

    float v[4];
    float m = -1e30f;
    #pragma unroll
    for (int i = 0; i < 4; i++) {
        v[i] = row[t + i * 256] * scale;
        m = fmaxf(m, v[i]);
    }
    #pragma unroll
    for (int o = 16; o > 0; o >>= 1) m = fmaxf(m, __shfl_xor_sync(~0u, m, o));
    if ((t & 31) == 0) red[t >> 5] = m;
    __syncthreads();
    if (t < 32) {
        float x = red[t & 7];
        #pragma unroll
        for (int o = 4; o > 0; o >>= 1) x = fmaxf(x, __shfl_xor_sync(~0u, x, o));
        red[t] = x;
    }
    __syncthreads();
    m = red[0];

    float sum = 0.f;
    #pragma unroll
    for (int i = 0; i < 4; i++) { v[i] = __expf(v[i] - m); sum += v[i]; }
    #pragma unroll
    for (int o = 16; o > 0; o >>= 1) sum += __shfl_xor_sync(~0u, sum, o);
    __syncthreads();
    if ((t & 31) == 0) red[t >> 5] = sum;
    __syncthreads();
    if (t < 32) {
        float x = red[t & 7];
        #pragma unroll
        for (int o = 4; o > 0; o >>= 1) x += __shfl_xor_sync(~0u, x, o);
        red[t] = x;
    }
    __syncthreads();
    float inv = 1.f / red[0];
    #pragma unroll
    for (int i = 0; i < 4; i++) row[t + i * 256] = rtf(v[i] * inv);
}

// ---------------------------------------------------------------------------
// Merge heads: a_m[bc][n*128+d][s] = av[bcn][s][d]; output tf32-rounded
// ---------------------------------------------------------------------------
__global__ __launch_bounds__(256)
void merge_heads(const float* __restrict__ av, float* __restrict__ am)
{
    __shared__ float tile[32][33];
    int bcn = blockIdx.z;
    const float* src = av + (long)bcn * (NB * HD);
    float*       dst = am + (long)bcn * (NB * HD);
    int d0 = blockIdx.x * 32, s0 = blockIdx.y * 32;
    int tx = threadIdx.x, ty = threadIdx.y;
    #pragma unroll
    for (int i = 0; i < 32; i += 8)
        tile[ty + i][tx] = src[(long)(s0 + ty + i) * HD + d0 + tx];
    __syncthreads();
    #pragma unroll
    for (int i = 0; i < 32; i += 8)
        dst[(long)(d0 + ty + i) * NB + s0 + tx] = rtf(tile[tx][ty + i]);
}

// ---------------------------------------------------------------------------
// Launch
// ---------------------------------------------------------------------------
extern "C" void kernel_launch(void* const* d_in, const int* in_sizes, int n_in,
                              void* d_out, int out_size)
{
    const float* x      = (const float*)d_in[0];  // (2,4,1024,1024)
    const float* w_lin  = (const float*)d_in[1];  // (4,1024,1024)
    const float* w_conv = (const float*)d_in[2];  // (4,1,1,3)
    const float* b_conv = (const float*)d_in[3];  // (4,)
    const float* w_out  = (const float*)d_in[4];  // (4,1024,1024)
    float* out = (float*)d_out;

    float *y, *p, *q, *s, *av, *am, *xc, *wl, *wo;
    cudaGetSymbolAddress((void**)&y,  g_y);
    cudaGetSymbolAddress((void**)&p,  g_p);
    cudaGetSymbolAddress((void**)&q,  g_q);
    cudaGetSymbolAddress((void**)&s,  g_s);
    cudaGetSymbolAddress((void**)&av, g_av);
    cudaGetSymbolAddress((void**)&am, g_am);
    cudaGetSymbolAddress((void**)&xc, g_xc);
    cudaGetSymbolAddress((void**)&wl, g_wl);
    cudaGetSymbolAddress((void**)&wo, g_wo);

    cudaFuncSetAttribute(gemm_tc, cudaFuncAttributeMaxDynamicSharedMemorySize, GEMM_SMEM);

    const long MM = (long)NB * NB;          // 1048576
    const long QS = (long)NB * HD;          // 131072

    // 0) pre-round GEMM inputs to tf32
    cvt_tf32<<<(int)(BC * MM / 4 / 256), 256>>>(x, xc, (int)(BC * MM / 4));
    cvt_tf32<<<(int)(CH * MM / 4 / 256), 256>>>(w_lin, wl, (int)(CH * MM / 4));
    cvt_tf32<<<(int)(CH * MM / 4 / 256), 256>>>(w_out, wo, (int)(CH * MM / 4));

    // 1) proj GEMM: y[bc] = x[bc] @ w_lin[c]^T
    gemm_tc<<<dim3(8, 8, BC), 128, GEMM_SMEM>>>(xc, wl, y,
        NB, NB, NB, NB, MM, MM, MM, CH, 0);

    // 2) depthwise conv3 + bias (writes tf32 p)
    conv_bias<<<(int)((BC * MM + 255) / 256), 256>>>(y, w_conv, b_conv, p);

    // 3) RoPE -> Q (== K), tf32
    rope_build<<<(int)(((long)BCN * 64 * NB + 255) / 256), 256>>>(p, q);

    // 4) scores = Q @ Q^T: symmetric -> upper-triangle tiles only + mirror
    gemm_tc<<<dim3(8, 8, BCN), 128, GEMM_SMEM>>>(q, q, s,
        HD, HD, HD, NB, QS, QS, MM, BCN, 1);

    // 5) softmax rows, scale = 1/sqrt(1024), writes tf32 probs
    softmax_rows<<<BCN * NB, 256>>>(s, 1.0f / 32.0f);

    // 6) av = P @ V   (V^T is the p slice: stride 131072 per bcn, ldb=1024)
    gemm_tc<<<dim3(1, 8, BCN), 128, GEMM_SMEM>>>(s, p, av,
        NB, NB, NB, HD, MM, QS, QS, BCN, 0);

    // 7) merge heads (batched transpose), writes tf32 am
    merge_heads<<<dim3(4, 32, BCN), dim3(32, 8)>>>(av, am);

    // 8) out GEMM: out[bc] = am[bc] @ w_out[c]^T
    gemm_tc<<<dim3(8, 8, BC), 128, GEMM_SMEM>>>(am, wo, out,
        NB, NB, NB, NB, MM, MM, MM, CH, 0);
}

// round 13
// speedup vs baseline: 1.0665x; 1.0665x over previous
#include <cuda_runtime.h>
#include <cuda_bf16.h>
#include <math.h>
#include <stdint.h>

// ---------------------------------------------------------------------------
// Problem constants: x(2,4,1024,1024), HEADS=8, D=128, ROT_DIM=64
// ---------------------------------------------------------------------------
#define BATCH   2
#define CH      4
#define BC      (BATCH*CH)        // 8
#define NB      1024              // BINS
#define NH      8                 // heads
#define HD      128               // head dim
#define BCN     (BC*NH)           // 64
#define ROT     64                // rotary dims

// Scratch (static __device__ — no allocations allowed)
__device__ float g_y [BC  * NB * NB];   // proj gemm out (pre-conv)      32MB
__device__ float g_p [BC  * NB * NB];   // conv+bias out (tf32, also V^T) 32MB
__device__ float g_q [BCN * NB * HD];   // roped Q (= K), tf32            32MB
__device__ float g_s [BCN * NB * NB];   // attention probs, tf32         256MB
__device__ float g_av[BCN * NB * HD];   // softmax @ V                    32MB
__device__ float g_am[BC  * NB * NB];   // merged heads, tf32             32MB
__device__ float g_xc[BC  * NB * NB];   // x converted to tf32            32MB
__device__ float g_wl[CH  * NB * NB];   // w_lin tf32                     16MB
__device__ float g_wo[CH  * NB * NB];   // w_out tf32                     16MB

// ---------------------------------------------------------------------------
// helpers
// ---------------------------------------------------------------------------
__device__ __forceinline__ unsigned f2tf32(float x) {
    unsigned r;
    asm("cvt.rna.tf32.f32 %0, %1;" : "=r"(r) : "f"(x));
    return r;
}
__device__ __forceinline__ float rtf(float x) { return __uint_as_float(f2tf32(x)); }

__device__ __forceinline__ uint32_t smem_u32(const void* p) {
    uint32_t a;
    asm("{ .reg .u64 t; cvta.to.shared.u64 t, %1; cvt.u32.u64 %0, t; }"
        : "=r"(a) : "l"(p));
    return a;
}

__device__ __forceinline__ void cp16(uint32_t dst, const void* src) {
    asm volatile("cp.async.ca.shared.global [%0], [%1], 16;" :: "r"(dst), "l"(src));
}

// cp.async arrive-on-mbarrier, NOINC (plain form is inc-then-arrive -> deadlock)
__device__ __forceinline__ void cp_arrive(uint32_t mbar) {
    asm volatile("cp.async.mbarrier.arrive.noinc.shared.b64 [%0];" :: "r"(mbar) : "memory");
}

#define MBAR_INIT(addr, cnt) \
    asm volatile("mbarrier.init.shared.b64 [%0], %1;" :: "r"(addr), "r"(cnt) : "memory")

__device__ __forceinline__ void mbar_arrive(uint32_t addr) {
    asm volatile("mbarrier.arrive.shared.b64 _, [%0];" :: "r"(addr) : "memory");
}

__device__ __forceinline__ void mbar_wait(uint32_t addr, uint32_t parity) {
    asm volatile(
        "{\n\t.reg .pred P1;\n\t"
        "WL_%=:\n\t"
        "mbarrier.try_wait.parity.acquire.cta.shared::cta.b64 P1, [%0], %1, 0x989680;\n\t"
        "@P1 bra.uni WD_%=;\n\t"
        "bra.uni WL_%=;\n\t"
        "WD_%=:\n\t}"
        :: "r"(addr), "r"(parity) : "memory");
}

// ldmatrix x4: tf32 data: lane i of each m8n8 tile gets fp32 element
// [i/4][i%4] -> exactly the m16n8k8 tf32 mma fragment layout.
__device__ __forceinline__ void ldsm4(unsigned& r0, unsigned& r1, unsigned& r2,
                                      unsigned& r3, uint32_t addr) {
    asm volatile("ldmatrix.sync.aligned.m8n8.x4.shared.b16 {%0,%1,%2,%3}, [%4];"
                 : "=r"(r0), "=r"(r1), "=r"(r2), "=r"(r3) : "r"(addr));
}

__device__ __forceinline__ void mma_tf32(float* d, const unsigned* a, const unsigned* b) {
    asm volatile(
        "mma.sync.aligned.m16n8k8.row.col.f32.tf32.tf32.f32 "
        "{%0,%1,%2,%3}, {%4,%5,%6,%7}, {%8,%9}, {%0,%1,%2,%3};"
        : "+f"(d[0]), "+f"(d[1]), "+f"(d[2]), "+f"(d[3])
        : "r"(a[0]), "r"(a[1]), "r"(a[2]), "r"(a[3]), "r"(b[0]), "r"(b[1]));
}

// ---------------------------------------------------------------------------
// elementwise tf32 rounding pass (for x, w_lin, w_out)
// ---------------------------------------------------------------------------
__global__ __launch_bounds__(256)
void cvt_tf32(const float* __restrict__ in, float* __restrict__ out, int n4)
{
    int i = blockIdx.x * 256 + threadIdx.x;
    if (i >= n4) return;
    float4 v = ((const float4*)in)[i];
    v.x = rtf(v.x); v.y = rtf(v.y); v.z = rtf(v.z); v.w = rtf(v.w);
    ((float4*)out)[i] = v;
}

// ---------------------------------------------------------------------------
// Batched NT GEMM, tensor cores (tf32, fp32 acc), inputs pre-rounded to tf32.
//   C[m,n] = sum_k A[m*lda+k] * B[n*ldb+k]
// 256 threads (8 warps, 2x4), block 128x128, warp tile 64x32 (4x4 m16n8k8).
// BK=16, FIVE smem slots, per-stage mbarrier pipeline (R11 design + deeper
// skew so producer empty-waits come off the critical path).
// full[s]: 256 cp.async-noinc arrivals; empty[s]: 8 warp arrivals.
// sym!=0 => symmetric C: CTAs with bn<bm exit; off-diag tiles mirror-store
// COALESCED via an smem transpose of the tile (stage smem reused post-loop).
// __launch_bounds__(256,2): 2 CTAs/SM; smem 2x~100KB = 200KB fits 228KB.
// ---------------------------------------------------------------------------
#define STG_F 5120          // floats per stage (2*128*20)
#define NSTG  5
#define GEMM_SMEM (96 + NSTG * STG_F * 4)   // 96B barriers + 100KB stages

__device__ __forceinline__ void issue_stage(uint32_t dbase, int slot,
    const float* Ag, const float* Bg, int kbase, int lda, int ldb, int tid)
{
    const int r  = tid >> 1;            // 0..127
    const int c0 = (tid & 1) * 8;       // 0 or 8
    uint32_t a_off = dbase + (uint32_t)(slot * STG_F + r * 20 + c0) * 4u;
    uint32_t b_off = a_off + 2560u * 4u;
    const float* ap = Ag + (long)r * lda + kbase + c0;
    const float* bp = Bg + (long)r * ldb + kbase + c0;
    cp16(a_off,      ap);
    cp16(a_off + 16, ap + 4);
    cp16(b_off,      bp);
    cp16(b_off + 16, bp + 4);
}

__global__ __launch_bounds__(256, 2)
void gemm_tc(const float* __restrict__ A, const float* __restrict__ B,
             float* __restrict__ C,
             int K, int lda, int ldb, int ldc,
             long sA, long sB, long sC, int modB, int sym)
{
    const int bm = blockIdx.y * 128;
    const int bn = blockIdx.x * 128;
    if (sym && bn < bm) return;          // symmetric: upper triangle only

    extern __shared__ float sm[];
    const uint32_t sbase = smem_u32(sm);     // full[5] @0, empty[5] @40
    const uint32_t dbase = sbase + 96;       // stage data
    float* stg = sm + 24;                    // same region (float index)

    const int tid = threadIdx.x;
    const int batch = blockIdx.z;

    const float* Ag = A + (long)batch * sA + (long)bm * lda;
    const float* Bg = B + (long)(batch % modB) * sB + (long)bn * ldb;
    C += (long)batch * sC;

    const int wid  = tid >> 5;
    const int lane = tid & 31;
    const int wm = wid & 1;             // 0..1 (64 rows)
    const int wn = wid >> 1;            // 0..3 (32 cols)
    const int g = lane >> 2;            // 0..7
    const int t = lane & 3;             // 0..3

    // ldmatrix per-lane address components
    const int a_ro = (lane & 7) + ((lane >> 3) & 1) * 8;   // 0..15
    const int a_co = (lane >> 4) * 4;                      // 0 or 4
    const int b_ro = (lane & 7) + (lane >> 4) * 8;         // 0..15
    const int b_co = ((lane >> 3) & 1) * 4;                // 0 or 4

    float acc[4][4][4];
    #pragma unroll
    for (int i = 0; i < 4; i++)
        #pragma unroll
        for (int j = 0; j < 4; j++)
            #pragma unroll
            for (int r = 0; r < 4; r++) acc[i][j][r] = 0.f;

    const int iters = K >> 4;           // BK = 16

    if (tid < NSTG) {
        MBAR_INIT(sbase + tid * 8, 256);        // full[tid]
        MBAR_INIT(sbase + 40 + tid * 8, 8);     // empty[tid]: one per warp
    }
    __syncthreads();

    // prefill stages 0..3 (first use of those slots: no empty wait)
    #pragma unroll
    for (int s = 0; s < 4; s++) {
        if (s < iters) {
            issue_stage(dbase, s, Ag, Bg, s * 16, lda, ldb, tid);
            cp_arrive(sbase + s * 8);
        }
    }

    // pipeline state (modulo-5, counter-based)
    int csl = 0, cph = 0;       // consumer slot / phase
    int psl = 4;                // producer slot for pn = it + 4 (starts at 4)
    int pph = 1;                // flips to 0 on first wrap (pn=5..9 wait parity 0)

    for (int it = 0; it < iters; ++it) {
        // 1) produce stage it+4
        const int pn = it + 4;
        if (pn < iters) {
            if (pn >= NSTG)  // slot reuse: wait for all warps to release it
                mbar_wait(sbase + 40 + psl * 8, pph);
            issue_stage(dbase, psl, Ag, Bg, pn * 16, lda, ldb, tid);
            cp_arrive(sbase + psl * 8);
        }
        psl++; if (psl == NSTG) { psl = 0; pph ^= 1; }

        // 2) wait for stage it
        mbar_wait(sbase + csl * 8, cph);

        const uint32_t aBase = dbase + (uint32_t)(csl * STG_F) * 4u;   // A [128][20]
        const uint32_t bBase = aBase + 2560u * 4u;                     // B [128][20]

        // 3) compute: 2 k-steps, frags via ldmatrix.x4
        #pragma unroll
        for (int ks = 0; ks < 2; ++ks) {
            const int k0 = ks * 8;
            unsigned af[4][4], bf[4][2];
            #pragma unroll
            for (int mt = 0; mt < 4; mt++) {
                uint32_t addr = aBase +
                    (uint32_t)(((wm * 64 + mt * 16 + a_ro) * 20) + k0 + a_co) * 4u;
                ldsm4(af[mt][0], af[mt][1], af[mt][2], af[mt][3], addr);
            }
            #pragma unroll
            for (int np = 0; np < 2; np++) {
                uint32_t addr = bBase +
                    (uint32_t)(((wn * 32 + np * 16 + b_ro) * 20) + k0 + b_co) * 4u;
                ldsm4(bf[2*np][0], bf[2*np][1], bf[2*np+1][0], bf[2*np+1][1], addr);
            }
            #pragma unroll
            for (int mt = 0; mt < 4; mt++)
                #pragma unroll
                for (int nt = 0; nt < 4; nt++)
                    mma_tf32(acc[mt][nt], af[mt], bf[nt]);
        }

        // 4) stage consumed -> warp-level release (lane 0; warp converged)
        if (lane == 0) mbar_arrive(sbase + 40 + csl * 8);
        csl++; if (csl == NSTG) { csl = 0; cph ^= 1; }
    }

    // epilogue: direct (coalesced) tile store
    #pragma unroll
    for (int mt = 0; mt < 4; mt++) {
        const int row = bm + wm * 64 + mt * 16 + g;
        #pragma unroll
        for (int nt = 0; nt < 4; nt++) {
            const int col = bn + wn * 32 + nt * 8 + 2 * t;
            float2 v0 = make_float2(acc[mt][nt][0], acc[mt][nt][1]);
            float2 v1 = make_float2(acc[mt][nt][2], acc[mt][nt][3]);
            *(float2*)(C + (long)row * ldc + col)       = v0;
            *(float2*)(C + (long)(row + 8) * ldc + col) = v1;
        }
    }

    if (sym && bm != bn) {
        // mirror tile C[bn..][bm..] = tile^T, via smem transpose for coalescing.
        // Stage smem is reused: sync so every warp is done with the k-loop.
        __syncthreads();
        float* T = stg;                      // [128][129], 66KB < 100KB
        #pragma unroll
        for (int mt = 0; mt < 4; mt++) {
            const int r = wm * 64 + mt * 16 + g;     // local row
            #pragma unroll
            for (int nt = 0; nt < 4; nt++) {
                const int c = wn * 32 + nt * 8 + 2 * t;   // local col
                T[(c    ) * 129 + r    ] = acc[mt][nt][0];
                T[(c + 1) * 129 + r    ] = acc[mt][nt][1];
                T[(c    ) * 129 + r + 8] = acc[mt][nt][2];
                T[(c + 1) * 129 + r + 8] = acc[mt][nt][3];
            }
        }
        __syncthreads();
        // write 128 rows of the mirror block, fully coalesced
        const int rr = tid >> 1;             // 0..127  (= local col c)
        const int ch = (tid & 1) * 64;       // column half within row
        float* crow = C + (long)(bn + rr) * ldc + bm + ch;
        const float* trow = T + rr * 129 + ch;
        #pragma unroll
        for (int j = 0; j < 64; j += 4) {
            float4 v = make_float4(trow[j], trow[j+1], trow[j+2], trow[j+3]);
            *(float4*)(crow + j) = v;
        }
    }
}

// ---------------------------------------------------------------------------
// Depthwise conv (kernel 3, pad 1 along last axis) + bias; output tf32-rounded
// ---------------------------------------------------------------------------
__global__ __launch_bounds__(256)
void conv_bias(const float* __restrict__ y, const float* __restrict__ wc,
               const float* __restrict__ bias, float* __restrict__ p)
{
    long idx = (long)blockIdx.x * blockDim.x + threadIdx.x;   // 8M elems
    if (idx >= (long)BC * NB * NB) return;
    int o = (int)(idx & (NB - 1));
    int c = (int)((idx >> 20) & 3);
    float w0 = wc[c*3+0], w1 = wc[c*3+1], w2 = wc[c*3+2];
    float mid = y[idx];
    float lft = (o > 0)      ? y[idx - 1] : 0.f;
    float rgt = (o < NB - 1) ? y[idx + 1] : 0.f;
    p[idx] = rtf(fmaf(lft, w0, fmaf(mid, w1, fmaf(rgt, w2, bias[c]))));
}

// ---------------------------------------------------------------------------
// RoPE + transpose: Q[bcn][s][d] from p[bc][n*128+d][s]; output tf32-rounded
// ---------------------------------------------------------------------------
__global__ __launch_bounds__(256)
void rope_build(const float* __restrict__ p, float* __restrict__ Q)
{
    long idx = (long)blockIdx.x * blockDim.x + threadIdx.x;   // 4M
    if (idx >= (long)BCN * 64 * NB) return;
    int s   = (int)(idx & (NB - 1));
    int j   = (int)((idx >> 10) & 63);
    int bcn = (int)(idx >> 16);
    int bc = bcn >> 3, n = bcn & 7;

    const float* src = p + ((long)bc * NB + n * HD) * NB + s;
    float*       dst = Q + (long)bcn * (NB * HD) + (long)s * HD;

    if (j < 32) {
        float t0 = src[(2*j + 0) * NB];
        float t1 = src[(2*j + 1) * NB];
        float invf = powf(10000.f, -(float)(2*j) / (float)ROT);
        float ang = (float)s * invf;
        float cs = cosf(ang), sn = sinf(ang);
        dst[2*j + 0] = rtf(t0 * cs - t1 * sn);
        dst[2*j + 1] = rtf(t1 * cs + t0 * sn);
    } else {
        int d = ROT + (j - 32) * 2;
        dst[d + 0] = src[(d + 0) * NB];
        dst[d + 1] = src[(d + 1) * NB];
    }
}

// ---------------------------------------------------------------------------
// Row softmax with scale (one block per row of 1024); float4 I/O; tf32 out
// ---------------------------------------------------------------------------
__global__ __launch_bounds__(256)
void softmax_rows(float* __restrict__ S, float scale)
{
    float4* row4 = (float4*)(S + (long)blockIdx.x * NB);
    const int t = threadIdx.x;
    __shared__ float red[32];

    float4 v = row4[t];
    v.x *= scale; v.y *= scale; v.z *= scale; v.w *= scale;
    float m = fmaxf(fmaxf(v.x, v.y), fmaxf(v.z, v.w));
    #pragma unroll
    for (int o = 16; o > 0; o >>= 1) m = fmaxf(m, __shfl_xor_sync(~0u, m, o));
    if ((t & 31) == 0) red[t >> 5] = m;
    __syncthreads();
    if (t < 32) {
        float x = red[t & 7];
        #pragma unroll
        for (int o = 4; o > 0; o >>= 1) x = fmaxf(x, __shfl_xor_sync(~0u, x, o));
        red[t] = x;
    }
    __syncthreads();
    m = red[0];

    v.x = __expf(v.x - m); v.y = __expf(v.y - m);
    v.z = __expf(v.z - m); v.w = __expf(v.w - m);
    float sum = v.x + v.y + v.z + v.w;
    #pragma unroll
    for (int o = 16; o > 0; o >>= 1) sum += __shfl_xor_sync(~0u, sum, o);
    __syncthreads();
    if ((t & 31) == 0) red[t >> 5] = sum;
    __syncthreads();
    if (t < 32) {
        float x = red[t & 7];
        #pragma unroll
        for (int o = 4; o > 0; o >>= 1) x += __shfl_xor_sync(~0u, x, o);
        red[t] = x;
    }
    __syncthreads();
    float inv = 1.f / red[0];
    v.x = rtf(v.x * inv); v.y = rtf(v.y * inv);
    v.z = rtf(v.z * inv); v.w = rtf(v.w * inv);
    row4[t] = v;
}

// ---------------------------------------------------------------------------
// Merge heads: a_m[bc][n*128+d][s] = av[bcn][s][d]; output tf32-rounded
// ---------------------------------------------------------------------------
__global__ __launch_bounds__(256)
void merge_heads(const float* __restrict__ av, float* __restrict__ am)
{
    __shared__ float tile[32][33];
    int bcn = blockIdx.z;
    const float* src = av + (long)bcn * (NB * HD);
    float*       dst = am + (long)bcn * (NB * HD);
    int d0 = blockIdx.x * 32, s0 = blockIdx.y * 32;
    int tx = threadIdx.x, ty = threadIdx.y;
    #pragma unroll
    for (int i = 0; i < 32; i += 8)
        tile[ty + i][tx] = src[(long)(s0 + ty + i) * HD + d0 + tx];
    __syncthreads();
    #pragma unroll
    for (int i = 0; i < 32; i += 8)
        dst[(long)(d0 + ty + i) * NB + s0 + tx] = rtf(tile[tx][ty + i]);
}

// ---------------------------------------------------------------------------
// Launch
// ---------------------------------------------------------------------------
extern "C" void kernel_launch(void* const* d_in, const int* in_sizes, int n_in,
                              void* d_out, int out_size)
{
    const float* x      = (const float*)d_in[0];  // (2,4,1024,1024)
    const float* w_lin  = (const float*)d_in[1];  // (4,1024,1024)
    const float* w_conv = (const float*)d_in[2];  // (4,1,1,3)
    const float* b_conv = (const float*)d_in[3];  // (4,)
    const float* w_out  = (const float*)d_in[4];  // (4,1024,1024)
    float* out = (float*)d_out;

    float *y, *p, *q, *s, *av, *am, *xc, *wl, *wo;
    cudaGetSymbolAddress((void**)&y,  g_y);
    cudaGetSymbolAddress((void**)&p,  g_p);
    cudaGetSymbolAddress((void**)&q,  g_q);
    cudaGetSymbolAddress((void**)&s,  g_s);
    cudaGetSymbolAddress((void**)&av, g_av);
    cudaGetSymbolAddress((void**)&am, g_am);
    cudaGetSymbolAddress((void**)&xc, g_xc);
    cudaGetSymbolAddress((void**)&wl, g_wl);
    cudaGetSymbolAddress((void**)&wo, g_wo);

    cudaFuncSetAttribute(gemm_tc, cudaFuncAttributeMaxDynamicSharedMemorySize, GEMM_SMEM);

    const long MM = (long)NB * NB;          // 1048576
    const long QS = (long)NB * HD;          // 131072

    // 0) pre-round GEMM inputs to tf32 (RNA; raw-fp32 feed would add a
    //    coherent ~1e-3 truncation bias across K=1024 — not safe)
    cvt_tf32<<<(int)(BC * MM / 4 / 256), 256>>>(x, xc, (int)(BC * MM / 4));
    cvt_tf32<<<(int)(CH * MM / 4 / 256), 256>>>(w_lin, wl, (int)(CH * MM / 4));
    cvt_tf32<<<(int)(CH * MM / 4 / 256), 256>>>(w_out, wo, (int)(CH * MM / 4));

    // 1) proj GEMM: y[bc] = x[bc] @ w_lin[c]^T
    gemm_tc<<<dim3(8, 8, BC), 256, GEMM_SMEM>>>(xc, wl, y,
        NB, NB, NB, NB, MM, MM, MM, CH, 0);

    // 2) depthwise conv3 + bias (writes tf32 p)
    conv_bias<<<(int)((BC * MM + 255) / 256), 256>>>(y, w_conv, b_conv, p);

    // 3) RoPE -> Q (== K), tf32
    rope_build<<<(int)(((long)BCN * 64 * NB + 255) / 256), 256>>>(p, q);

    // 4) scores = Q @ Q^T: symmetric -> upper-triangle tiles only + mirror
    gemm_tc<<<dim3(8, 8, BCN), 256, GEMM_SMEM>>>(q, q, s,
        HD, HD, HD, NB, QS, QS, MM, BCN, 1);

    // 5) softmax rows, scale = 1/sqrt(1024), writes tf32 probs
    softmax_rows<<<BCN * NB, 256>>>(s, 1.0f / 32.0f);

    // 6) av = P @ V   (V^T is the p slice: stride 131072 per bcn, ldb=1024)
    gemm_tc<<<dim3(1, 8, BCN), 256, GEMM_SMEM>>>(s, p, av,
        NB, NB, NB, HD, MM, QS, QS, BCN, 0);

    // 7) merge heads (batched transpose), writes tf32 am
    merge_heads<<<dim3(4, 32, BCN), dim3(32, 8)>>>(av, am);

    // 8) out GEMM: out[bc] = am[bc] @ w_out[c]^T
    gemm_tc<<<dim3(8, 8, BC), 256, GEMM_SMEM>>>(am, wo, out,
        NB, NB, NB, NB, MM, MM, MM, CH, 0);
}

// round 14
// speedup vs baseline: 1.1940x; 1.1196x over previous
#include <cuda_runtime.h>
#include <cuda_bf16.h>
#include <math.h>
#include <stdint.h>

// ---------------------------------------------------------------------------
// Problem constants: x(2,4,1024,1024), HEADS=8, D=128, ROT_DIM=64
// ---------------------------------------------------------------------------
#define BATCH   2
#define CH      4
#define BC      (BATCH*CH)        // 8
#define NB      1024              // BINS
#define NH      8                 // heads
#define HD      128               // head dim
#define BCN     (BC*NH)           // 64
#define ROT     64                // rotary dims

// Scratch (static __device__ — no allocations allowed)
__device__ float g_y [BC  * NB * NB];   // proj gemm out (pre-conv)      32MB
__device__ float g_p [BC  * NB * NB];   // conv+bias out (tf32, also V^T) 32MB
__device__ float g_q [BCN * NB * HD];   // roped Q (= K), tf32            32MB
__device__ float g_s [BCN * NB * NB];   // attention probs, tf32         256MB
__device__ float g_av[BCN * NB * HD];   // softmax @ V                    32MB
__device__ float g_am[BC  * NB * NB];   // merged heads, tf32             32MB
__device__ float g_xc[BC  * NB * NB];   // x converted to tf32            32MB
__device__ float g_wl[CH  * NB * NB];   // w_lin tf32                     16MB
__device__ float g_wo[CH  * NB * NB];   // w_out tf32                     16MB

// ---------------------------------------------------------------------------
// helpers
// ---------------------------------------------------------------------------
__device__ __forceinline__ unsigned f2tf32(float x) {
    unsigned r;
    asm("cvt.rna.tf32.f32 %0, %1;" : "=r"(r) : "f"(x));
    return r;
}
__device__ __forceinline__ float rtf(float x) { return __uint_as_float(f2tf32(x)); }

__device__ __forceinline__ uint32_t smem_u32(const void* p) {
    uint32_t a;
    asm("{ .reg .u64 t; cvta.to.shared.u64 t, %1; cvt.u32.u64 %0, t; }"
        : "=r"(a) : "l"(p));
    return a;
}

__device__ __forceinline__ void cp16(uint32_t dst, const void* src) {
    asm volatile("cp.async.ca.shared.global [%0], [%1], 16;" :: "r"(dst), "l"(src));
}

// cp.async arrive-on-mbarrier, NOINC (plain form is inc-then-arrive -> deadlock)
__device__ __forceinline__ void cp_arrive(uint32_t mbar) {
    asm volatile("cp.async.mbarrier.arrive.noinc.shared.b64 [%0];" :: "r"(mbar) : "memory");
}

#define MBAR_INIT(addr, cnt) \
    asm volatile("mbarrier.init.shared.b64 [%0], %1;" :: "r"(addr), "r"(cnt) : "memory")

__device__ __forceinline__ void mbar_arrive(uint32_t addr) {
    asm volatile("mbarrier.arrive.shared.b64 _, [%0];" :: "r"(addr) : "memory");
}

__device__ __forceinline__ void mbar_wait(uint32_t addr, uint32_t parity) {
    asm volatile(
        "{\n\t.reg .pred P1;\n\t"
        "WL_%=:\n\t"
        "mbarrier.try_wait.parity.acquire.cta.shared::cta.b64 P1, [%0], %1, 0x989680;\n\t"
        "@P1 bra.uni WD_%=;\n\t"
        "bra.uni WL_%=;\n\t"
        "WD_%=:\n\t}"
        :: "r"(addr), "r"(parity) : "memory");
}

// ldmatrix x4: tf32 data: lane i of each m8n8 tile gets fp32 element
// [i/4][i%4] -> exactly the m16n8k8 tf32 mma fragment layout.
__device__ __forceinline__ void ldsm4(unsigned& r0, unsigned& r1, unsigned& r2,
                                      unsigned& r3, uint32_t addr) {
    asm volatile("ldmatrix.sync.aligned.m8n8.x4.shared.b16 {%0,%1,%2,%3}, [%4];"
                 : "=r"(r0), "=r"(r1), "=r"(r2), "=r"(r3) : "r"(addr));
}

__device__ __forceinline__ void mma_tf32(float* d, const unsigned* a, const unsigned* b) {
    asm volatile(
        "mma.sync.aligned.m16n8k8.row.col.f32.tf32.tf32.f32 "
        "{%0,%1,%2,%3}, {%4,%5,%6,%7}, {%8,%9}, {%0,%1,%2,%3};"
        : "+f"(d[0]), "+f"(d[1]), "+f"(d[2]), "+f"(d[3])
        : "r"(a[0]), "r"(a[1]), "r"(a[2]), "r"(a[3]), "r"(b[0]), "r"(b[1]));
}

// ---------------------------------------------------------------------------
// elementwise tf32 rounding pass (for x, w_lin, w_out)
// ---------------------------------------------------------------------------
__global__ __launch_bounds__(256)
void cvt_tf32(const float* __restrict__ in, float* __restrict__ out, int n4)
{
    int i = blockIdx.x * 256 + threadIdx.x;
    if (i >= n4) return;
    float4 v = ((const float4*)in)[i];
    v.x = rtf(v.x); v.y = rtf(v.y); v.z = rtf(v.z); v.w = rtf(v.w);
    ((float4*)out)[i] = v;
}

// ---------------------------------------------------------------------------
// Batched NT GEMM, tensor cores (tf32, fp32 acc), inputs pre-rounded to tf32.
//   C[m,n] = sum_k A[m*lda+k] * B[n*ldb+k]
// 256 threads (8 warps, 2x4), block 128x128, warp tile 64x32 (4x4 m16n8k8).
// BK=16, FOUR smem slots (power-of-two masks — R13 showed counter-based
// 5-stage indexing + extra smem costs more than the added depth buys).
// Per-stage mbarrier pipeline: full[s] 256 cp.async-noinc arrivals,
// empty[s] 8 warp arrivals (lane 0; warp converged).
// Frags via ldmatrix.x4 on stride-20 rows (conflict-free).
// sym!=0 => symmetric C: CTAs with bn<bm exit; off-diag tiles mirror-store
// COALESCED via an smem transpose (stage smem reused after the k-loop).
// __launch_bounds__(256,2): 2 CTAs/SM; smem 2x80KB.
// ---------------------------------------------------------------------------
#define STG_F 5120          // floats per stage (2*128*20)
#define NSTG  4
#define GEMM_SMEM (64 + NSTG * STG_F * 4)   // 64B barriers + 80KB stages

__device__ __forceinline__ void issue_stage(uint32_t dbase, int slot,
    const float* Ag, const float* Bg, int kbase, int lda, int ldb, int tid)
{
    const int r  = tid >> 1;            // 0..127
    const int c0 = (tid & 1) * 8;       // 0 or 8
    uint32_t a_off = dbase + (uint32_t)(slot * STG_F + r * 20 + c0) * 4u;
    uint32_t b_off = a_off + 2560u * 4u;
    const float* ap = Ag + (long)r * lda + kbase + c0;
    const float* bp = Bg + (long)r * ldb + kbase + c0;
    cp16(a_off,      ap);
    cp16(a_off + 16, ap + 4);
    cp16(b_off,      bp);
    cp16(b_off + 16, bp + 4);
}

__global__ __launch_bounds__(256, 2)
void gemm_tc(const float* __restrict__ A, const float* __restrict__ B,
             float* __restrict__ C,
             int K, int lda, int ldb, int ldc,
             long sA, long sB, long sC, int modB, int sym)
{
    const int bm = blockIdx.y * 128;
    const int bn = blockIdx.x * 128;
    if (sym && bn < bm) return;          // symmetric: upper triangle only

    extern __shared__ float sm[];
    const uint32_t sbase = smem_u32(sm);     // full[4] @0, empty[4] @32
    const uint32_t dbase = sbase + 64;       // stage data
    float* stg = sm + 16;                    // same region (float index)

    const int tid = threadIdx.x;
    const int batch = blockIdx.z;

    const float* Ag = A + (long)batch * sA + (long)bm * lda;
    const float* Bg = B + (long)(batch % modB) * sB + (long)bn * ldb;
    C += (long)batch * sC;

    const int wid  = tid >> 5;
    const int lane = tid & 31;
    const int wm = wid & 1;             // 0..1 (64 rows)
    const int wn = wid >> 1;            // 0..3 (32 cols)
    const int g = lane >> 2;            // 0..7
    const int t = lane & 3;             // 0..3

    // ldmatrix per-lane address components
    const int a_ro = (lane & 7) + ((lane >> 3) & 1) * 8;   // 0..15
    const int a_co = (lane >> 4) * 4;                      // 0 or 4
    const int b_ro = (lane & 7) + (lane >> 4) * 8;         // 0..15
    const int b_co = ((lane >> 3) & 1) * 4;                // 0 or 4

    float acc[4][4][4];
    #pragma unroll
    for (int i = 0; i < 4; i++)
        #pragma unroll
        for (int j = 0; j < 4; j++)
            #pragma unroll
            for (int r = 0; r < 4; r++) acc[i][j][r] = 0.f;

    const int iters = K >> 4;           // BK = 16

    if (tid < NSTG) {
        MBAR_INIT(sbase + tid * 8, 256);        // full[tid]
        MBAR_INIT(sbase + 32 + tid * 8, 8);     // empty[tid]: one per warp
    }
    __syncthreads();

    // prefill stages 0..2
    #pragma unroll
    for (int s = 0; s < 3; s++) {
        issue_stage(dbase, s, Ag, Bg, s * 16, lda, ldb, tid);
        cp_arrive(sbase + s * 8);
    }

    for (int it = 0; it < iters; ++it) {
        // 1) produce stage it+3
        const int pn = it + 3;
        if (pn < iters) {
            const int ps = pn & 3;
            if (pn >= NSTG)
                mbar_wait(sbase + 32 + ps * 8, ((pn >> 2) - 1) & 1);
            issue_stage(dbase, ps, Ag, Bg, pn * 16, lda, ldb, tid);
            cp_arrive(sbase + ps * 8);
        }

        // 2) wait for stage it
        const int slot = it & 3;
        mbar_wait(sbase + slot * 8, (it >> 2) & 1);

        const uint32_t aBase = dbase + (uint32_t)(slot * STG_F) * 4u;   // A [128][20]
        const uint32_t bBase = aBase + 2560u * 4u;                      // B [128][20]

        // 3) compute: 2 k-steps, frags via ldmatrix.x4
        #pragma unroll
        for (int ks = 0; ks < 2; ++ks) {
            const int k0 = ks * 8;
            unsigned af[4][4], bf[4][2];
            #pragma unroll
            for (int mt = 0; mt < 4; mt++) {
                uint32_t addr = aBase +
                    (uint32_t)(((wm * 64 + mt * 16 + a_ro) * 20) + k0 + a_co) * 4u;
                ldsm4(af[mt][0], af[mt][1], af[mt][2], af[mt][3], addr);
            }
            #pragma unroll
            for (int np = 0; np < 2; np++) {
                uint32_t addr = bBase +
                    (uint32_t)(((wn * 32 + np * 16 + b_ro) * 20) + k0 + b_co) * 4u;
                ldsm4(bf[2*np][0], bf[2*np][1], bf[2*np+1][0], bf[2*np+1][1], addr);
            }
            #pragma unroll
            for (int mt = 0; mt < 4; mt++)
                #pragma unroll
                for (int nt = 0; nt < 4; nt++)
                    mma_tf32(acc[mt][nt], af[mt], bf[nt]);
        }

        // 4) stage consumed -> warp-level release (lane 0; warp converged)
        if (lane == 0) mbar_arrive(sbase + 32 + slot * 8);
    }

    // epilogue: direct (coalesced) tile store
    #pragma unroll
    for (int mt = 0; mt < 4; mt++) {
        const int row = bm + wm * 64 + mt * 16 + g;
        #pragma unroll
        for (int nt = 0; nt < 4; nt++) {
            const int col = bn + wn * 32 + nt * 8 + 2 * t;
            float2 v0 = make_float2(acc[mt][nt][0], acc[mt][nt][1]);
            float2 v1 = make_float2(acc[mt][nt][2], acc[mt][nt][3]);
            *(float2*)(C + (long)row * ldc + col)       = v0;
            *(float2*)(C + (long)(row + 8) * ldc + col) = v1;
        }
    }

    if (sym && bm != bn) {
        // mirror tile C[bn..][bm..] = tile^T via smem transpose (coalesced).
        __syncthreads();                     // all warps done with stage smem
        float* T = stg;                      // [128][129], 66KB < 80KB
        #pragma unroll
        for (int mt = 0; mt < 4; mt++) {
            const int r = wm * 64 + mt * 16 + g;          // local row
            #pragma unroll
            for (int nt = 0; nt < 4; nt++) {
                const int c = wn * 32 + nt * 8 + 2 * t;   // local col
                T[(c    ) * 129 + r    ] = acc[mt][nt][0];
                T[(c + 1) * 129 + r    ] = acc[mt][nt][1];
                T[(c    ) * 129 + r + 8] = acc[mt][nt][2];
                T[(c + 1) * 129 + r + 8] = acc[mt][nt][3];
            }
        }
        __syncthreads();
        const int rr = tid >> 1;             // 0..127  (= local col)
        const int ch = (tid & 1) * 64;       // half-row offset
        float* crow = C + (long)(bn + rr) * ldc + bm + ch;
        const float* trow = T + rr * 129 + ch;
        #pragma unroll
        for (int j = 0; j < 64; j += 4) {
            float4 v = make_float4(trow[j], trow[j+1], trow[j+2], trow[j+3]);
            *(float4*)(crow + j) = v;
        }
    }
}

// ---------------------------------------------------------------------------
// Depthwise conv (kernel 3, pad 1 along last axis) + bias; output tf32-rounded
// ---------------------------------------------------------------------------
__global__ __launch_bounds__(256)
void conv_bias(const float* __restrict__ y, const float* __restrict__ wc,
               const float* __restrict__ bias, float* __restrict__ p)
{
    long idx = (long)blockIdx.x * blockDim.x + threadIdx.x;   // 8M elems
    if (idx >= (long)BC * NB * NB) return;
    int o = (int)(idx & (NB - 1));
    int c = (int)((idx >> 20) & 3);
    float w0 = wc[c*3+0], w1 = wc[c*3+1], w2 = wc[c*3+2];
    float mid = y[idx];
    float lft = (o > 0)      ? y[idx - 1] : 0.f;
    float rgt = (o < NB - 1) ? y[idx + 1] : 0.f;
    p[idx] = rtf(fmaf(lft, w0, fmaf(mid, w1, fmaf(rgt, w2, bias[c]))));
}

// ---------------------------------------------------------------------------
// RoPE + transpose: Q[bcn][s][d] from p[bc][n*128+d][s]; output tf32-rounded
// ---------------------------------------------------------------------------
__global__ __launch_bounds__(256)
void rope_build(const float* __restrict__ p, float* __restrict__ Q)
{
    long idx = (long)blockIdx.x * blockDim.x + threadIdx.x;   // 4M
    if (idx >= (long)BCN * 64 * NB) return;
    int s   = (int)(idx & (NB - 1));
    int j   = (int)((idx >> 10) & 63);
    int bcn = (int)(idx >> 16);
    int bc = bcn >> 3, n = bcn & 7;

    const float* src = p + ((long)bc * NB + n * HD) * NB + s;
    float*       dst = Q + (long)bcn * (NB * HD) + (long)s * HD;

    if (j < 32) {
        float t0 = src[(2*j + 0) * NB];
        float t1 = src[(2*j + 1) * NB];
        float invf = powf(10000.f, -(float)(2*j) / (float)ROT);
        float ang = (float)s * invf;
        float cs = cosf(ang), sn = sinf(ang);
        dst[2*j + 0] = rtf(t0 * cs - t1 * sn);
        dst[2*j + 1] = rtf(t1 * cs + t0 * sn);
    } else {
        int d = ROT + (j - 32) * 2;
        dst[d + 0] = src[(d + 0) * NB];
        dst[d + 1] = src[(d + 1) * NB];
    }
}

// ---------------------------------------------------------------------------
// Row softmax with scale (one block per row of 1024); float4 I/O; tf32 out
// ---------------------------------------------------------------------------
__global__ __launch_bounds__(256)
void softmax_rows(float* __restrict__ S, float scale)
{
    float4* row4 = (float4*)(S + (long)blockIdx.x * NB);
    const int t = threadIdx.x;
    __shared__ float red[32];

    float4 v = row4[t];
    v.x *= scale; v.y *= scale; v.z *= scale; v.w *= scale;
    float m = fmaxf(fmaxf(v.x, v.y), fmaxf(v.z, v.w));
    #pragma unroll
    for (int o = 16; o > 0; o >>= 1) m = fmaxf(m, __shfl_xor_sync(~0u, m, o));
    if ((t & 31) == 0) red[t >> 5] = m;
    __syncthreads();
    if (t < 32) {
        float x = red[t & 7];
        #pragma unroll
        for (int o = 4; o > 0; o >>= 1) x = fmaxf(x, __shfl_xor_sync(~0u, x, o));
        red[t] = x;
    }
    __syncthreads();
    m = red[0];

    v.x = __expf(v.x - m); v.y = __expf(v.y - m);
    v.z = __expf(v.z - m); v.w = __expf(v.w - m);
    float sum = v.x + v.y + v.z + v.w;
    #pragma unroll
    for (int o = 16; o > 0; o >>= 1) sum += __shfl_xor_sync(~0u, sum, o);
    __syncthreads();
    if ((t & 31) == 0) red[t >> 5] = sum;
    __syncthreads();
    if (t < 32) {
        float x = red[t & 7];
        #pragma unroll
        for (int o = 4; o > 0; o >>= 1) x += __shfl_xor_sync(~0u, x, o);
        red[t] = x;
    }
    __syncthreads();
    float inv = 1.f / red[0];
    v.x = rtf(v.x * inv); v.y = rtf(v.y * inv);
    v.z = rtf(v.z * inv); v.w = rtf(v.w * inv);
    row4[t] = v;
}

// ---------------------------------------------------------------------------
// Merge heads: a_m[bc][n*128+d][s] = av[bcn][s][d]; output tf32-rounded
// ---------------------------------------------------------------------------
__global__ __launch_bounds__(256)
void merge_heads(const float* __restrict__ av, float* __restrict__ am)
{
    __shared__ float tile[32][33];
    int bcn = blockIdx.z;
    const float* src = av + (long)bcn * (NB * HD);
    float*       dst = am + (long)bcn * (NB * HD);
    int d0 = blockIdx.x * 32, s0 = blockIdx.y * 32;
    int tx = threadIdx.x, ty = threadIdx.y;
    #pragma unroll
    for (int i = 0; i < 32; i += 8)
        tile[ty + i][tx] = src[(long)(s0 + ty + i) * HD + d0 + tx];
    __syncthreads();
    #pragma unroll
    for (int i = 0; i < 32; i += 8)
        dst[(long)(d0 + ty + i) * NB + s0 + tx] = rtf(tile[tx][ty + i]);
}

// ---------------------------------------------------------------------------
// Launch
// ---------------------------------------------------------------------------
extern "C" void kernel_launch(void* const* d_in, const int* in_sizes, int n_in,
                              void* d_out, int out_size)
{
    const float* x      = (const float*)d_in[0];  // (2,4,1024,1024)
    const float* w_lin  = (const float*)d_in[1];  // (4,1024,1024)
    const float* w_conv = (const float*)d_in[2];  // (4,1,1,3)
    const float* b_conv = (const float*)d_in[3];  // (4,)
    const float* w_out  = (const float*)d_in[4];  // (4,1024,1024)
    float* out = (float*)d_out;

    float *y, *p, *q, *s, *av, *am, *xc, *wl, *wo;
    cudaGetSymbolAddress((void**)&y,  g_y);
    cudaGetSymbolAddress((void**)&p,  g_p);
    cudaGetSymbolAddress((void**)&q,  g_q);
    cudaGetSymbolAddress((void**)&s,  g_s);
    cudaGetSymbolAddress((void**)&av, g_av);
    cudaGetSymbolAddress((void**)&am, g_am);
    cudaGetSymbolAddress((void**)&xc, g_xc);
    cudaGetSymbolAddress((void**)&wl, g_wl);
    cudaGetSymbolAddress((void**)&wo, g_wo);

    cudaFuncSetAttribute(gemm_tc, cudaFuncAttributeMaxDynamicSharedMemorySize, GEMM_SMEM);

    const long MM = (long)NB * NB;          // 1048576
    const long QS = (long)NB * HD;          // 131072

    // 0) pre-round GEMM inputs to tf32
    cvt_tf32<<<(int)(BC * MM / 4 / 256), 256>>>(x, xc, (int)(BC * MM / 4));
    cvt_tf32<<<(int)(CH * MM / 4 / 256), 256>>>(w_lin, wl, (int)(CH * MM / 4));
    cvt_tf32<<<(int)(CH * MM / 4 / 256), 256>>>(w_out, wo, (int)(CH * MM / 4));

    // 1) proj GEMM: y[bc] = x[bc] @ w_lin[c]^T
    gemm_tc<<<dim3(8, 8, BC), 256, GEMM_SMEM>>>(xc, wl, y,
        NB, NB, NB, NB, MM, MM, MM, CH, 0);

    // 2) depthwise conv3 + bias (writes tf32 p)
    conv_bias<<<(int)((BC * MM + 255) / 256), 256>>>(y, w_conv, b_conv, p);

    // 3) RoPE -> Q (== K), tf32
    rope_build<<<(int)(((long)BCN * 64 * NB + 255) / 256), 256>>>(p, q);

    // 4) scores = Q @ Q^T: symmetric -> upper-triangle tiles only + mirror
    gemm_tc<<<dim3(8, 8, BCN), 256, GEMM_SMEM>>>(q, q, s,
        HD, HD, HD, NB, QS, QS, MM, BCN, 1);

    // 5) softmax rows, scale = 1/sqrt(1024), writes tf32 probs
    softmax_rows<<<BCN * NB, 256>>>(s, 1.0f / 32.0f);

    // 6) av = P @ V   (V^T is the p slice: stride 131072 per bcn, ldb=1024)
    gemm_tc<<<dim3(1, 8, BCN), 256, GEMM_SMEM>>>(s, p, av,
        NB, NB, NB, HD, MM, QS, QS, BCN, 0);

    // 7) merge heads (batched transpose), writes tf32 am
    merge_heads<<<dim3(4, 32, BCN), dim3(32, 8)>>>(av, am);

    // 8) out GEMM: out[bc] = am[bc] @ w_out[c]^T
    gemm_tc<<<dim3(8, 8, BC), 256, GEMM_SMEM>>>(am, wo, out,
        NB, NB, NB, NB, MM, MM, MM, CH, 0);
}

// round 15
// speedup vs baseline: 1.2558x; 1.0517x over previous
#include <cuda_runtime.h>
#include <cuda_bf16.h>
#include <math.h>
#include <stdint.h>

// ---------------------------------------------------------------------------
// Problem constants: x(2,4,1024,1024), HEADS=8, D=128, ROT_DIM=64
// ---------------------------------------------------------------------------
#define BATCH   2
#define CH      4
#define BC      (BATCH*CH)        // 8
#define NB      1024              // BINS
#define NH      8                 // heads
#define HD      128               // head dim
#define BCN     (BC*NH)           // 64
#define ROT     64                // rotary dims

// Scratch (static __device__ — no allocations allowed)
__device__ float g_y [BC  * NB * NB];   // proj gemm out (pre-conv)      32MB
__device__ float g_p [BC  * NB * NB];   // conv+bias out (tf32, also V^T) 32MB
__device__ float g_q [BCN * NB * HD];   // roped Q (= K), tf32            32MB
__device__ float g_s [BCN * NB * NB];   // attention probs, tf32         256MB
__device__ float g_av[BCN * NB * HD];   // softmax @ V                    32MB
__device__ float g_am[BC  * NB * NB];   // merged heads, tf32             32MB
__device__ float g_xc[BC  * NB * NB];   // x converted to tf32            32MB
__device__ float g_wl[CH  * NB * NB];   // w_lin tf32                     16MB
__device__ float g_wo[CH  * NB * NB];   // w_out tf32                     16MB

// ---------------------------------------------------------------------------
// helpers
// ---------------------------------------------------------------------------
__device__ __forceinline__ unsigned f2tf32(float x) {
    unsigned r;
    asm("cvt.rna.tf32.f32 %0, %1;" : "=r"(r) : "f"(x));
    return r;
}
__device__ __forceinline__ float rtf(float x) { return __uint_as_float(f2tf32(x)); }

__device__ __forceinline__ uint32_t smem_u32(const void* p) {
    uint32_t a;
    asm("{ .reg .u64 t; cvta.to.shared.u64 t, %1; cvt.u32.u64 %0, t; }"
        : "=r"(a) : "l"(p));
    return a;
}

__device__ __forceinline__ void cp16(uint32_t dst, const void* src) {
    asm volatile("cp.async.ca.shared.global [%0], [%1], 16;" :: "r"(dst), "l"(src));
}

// cp.async arrive-on-mbarrier, NOINC (plain form is inc-then-arrive -> deadlock)
__device__ __forceinline__ void cp_arrive(uint32_t mbar) {
    asm volatile("cp.async.mbarrier.arrive.noinc.shared.b64 [%0];" :: "r"(mbar) : "memory");
}

#define MBAR_INIT(addr, cnt) \
    asm volatile("mbarrier.init.shared.b64 [%0], %1;" :: "r"(addr), "r"(cnt) : "memory")

__device__ __forceinline__ void mbar_arrive(uint32_t addr) {
    asm volatile("mbarrier.arrive.shared.b64 _, [%0];" :: "r"(addr) : "memory");
}

__device__ __forceinline__ void mbar_wait(uint32_t addr, uint32_t parity) {
    asm volatile(
        "{\n\t.reg .pred P1;\n\t"
        "WL_%=:\n\t"
        "mbarrier.try_wait.parity.acquire.cta.shared::cta.b64 P1, [%0], %1, 0x989680;\n\t"
        "@P1 bra.uni WD_%=;\n\t"
        "bra.uni WL_%=;\n\t"
        "WD_%=:\n\t}"
        :: "r"(addr), "r"(parity) : "memory");
}

// ldmatrix x4: tf32 data: lane i of each m8n8 tile gets fp32 element
// [i/4][i%4] -> exactly the m16n8k8 tf32 mma fragment layout.
__device__ __forceinline__ void ldsm4(unsigned& r0, unsigned& r1, unsigned& r2,
                                      unsigned& r3, uint32_t addr) {
    asm volatile("ldmatrix.sync.aligned.m8n8.x4.shared.b16 {%0,%1,%2,%3}, [%4];"
                 : "=r"(r0), "=r"(r1), "=r"(r2), "=r"(r3) : "r"(addr));
}

__device__ __forceinline__ void mma_tf32(float* d, const unsigned* a, const unsigned* b) {
    asm volatile(
        "mma.sync.aligned.m16n8k8.row.col.f32.tf32.tf32.f32 "
        "{%0,%1,%2,%3}, {%4,%5,%6,%7}, {%8,%9}, {%0,%1,%2,%3};"
        : "+f"(d[0]), "+f"(d[1]), "+f"(d[2]), "+f"(d[3])
        : "r"(a[0]), "r"(a[1]), "r"(a[2]), "r"(a[3]), "r"(b[0]), "r"(b[1]));
}

// ---------------------------------------------------------------------------
// elementwise tf32 rounding pass (for x, w_lin, w_out)
// ---------------------------------------------------------------------------
__global__ __launch_bounds__(256)
void cvt_tf32(const float* __restrict__ in, float* __restrict__ out, int n4)
{
    int i = blockIdx.x * 256 + threadIdx.x;
    if (i >= n4) return;
    float4 v = ((const float4*)in)[i];
    v.x = rtf(v.x); v.y = rtf(v.y); v.z = rtf(v.z); v.w = rtf(v.w);
    ((float4*)out)[i] = v;
}

// ---------------------------------------------------------------------------
// Batched NT GEMM, tensor cores (tf32, fp32 acc), inputs pre-rounded to tf32.
//   C[m,n] = sum_k A[m*lda+k] * B[n*ldb+k]
// EXACT R11 champion configuration: 256 threads (8 warps, 2x4), block
// 128x128, warp tile 64x32 (4x4 m16n8k8), BK=16, 4 smem slots, per-stage
// mbarrier pipeline (full: 256 cp.async-noinc arrivals; empty: 8 warp
// arrivals), frags via ldmatrix.x4, stride-20 rows (conflict-free).
// sym!=0 => symmetric C: CTAs with bn<bm exit; off-diag tiles mirror-store
// (scalar fire-and-forget STGs — the R14 smem-transpose variant regressed).
// __launch_bounds__(256,2): 2 CTAs/SM; smem 2x80KB.
// ---------------------------------------------------------------------------
#define STG_F 5120          // floats per stage (2*128*20)
#define NSTG  4
#define GEMM_SMEM (64 + NSTG * STG_F * 4)   // 64B barriers + 80KB stages

__device__ __forceinline__ void issue_stage(uint32_t dbase, int slot,
    const float* Ag, const float* Bg, int kbase, int lda, int ldb, int tid)
{
    const int r  = tid >> 1;            // 0..127
    const int c0 = (tid & 1) * 8;       // 0 or 8
    uint32_t a_off = dbase + (uint32_t)(slot * STG_F + r * 20 + c0) * 4u;
    uint32_t b_off = a_off + 2560u * 4u;
    const float* ap = Ag + (long)r * lda + kbase + c0;
    const float* bp = Bg + (long)r * ldb + kbase + c0;
    cp16(a_off,      ap);
    cp16(a_off + 16, ap + 4);
    cp16(b_off,      bp);
    cp16(b_off + 16, bp + 4);
}

__global__ __launch_bounds__(256, 2)
void gemm_tc(const float* __restrict__ A, const float* __restrict__ B,
             float* __restrict__ C,
             int K, int lda, int ldb, int ldc,
             long sA, long sB, long sC, int modB, int sym)
{
    const int bm = blockIdx.y * 128;
    const int bn = blockIdx.x * 128;
    if (sym && bn < bm) return;          // symmetric: upper triangle only

    extern __shared__ float sm[];
    const uint32_t sbase = smem_u32(sm);     // barriers: full[4] @0, empty[4] @32
    const uint32_t dbase = sbase + 64;       // stage data

    const int tid = threadIdx.x;
    const int batch = blockIdx.z;

    const float* Ag = A + (long)batch * sA + (long)bm * lda;
    const float* Bg = B + (long)(batch % modB) * sB + (long)bn * ldb;
    C += (long)batch * sC;

    const int wid  = tid >> 5;
    const int lane = tid & 31;
    const int wm = wid & 1;             // 0..1 (64 rows)
    const int wn = wid >> 1;            // 0..3 (32 cols)
    const int g = lane >> 2;            // 0..7
    const int t = lane & 3;             // 0..3

    // ldmatrix per-lane address components (row/col offsets within warp tile)
    const int a_ro = (lane & 7) + ((lane >> 3) & 1) * 8;   // 0..15
    const int a_co = (lane >> 4) * 4;                      // 0 or 4
    const int b_ro = (lane & 7) + (lane >> 4) * 8;         // 0..15
    const int b_co = ((lane >> 3) & 1) * 4;                // 0 or 4

    float acc[4][4][4];
    #pragma unroll
    for (int i = 0; i < 4; i++)
        #pragma unroll
        for (int j = 0; j < 4; j++)
            #pragma unroll
            for (int r = 0; r < 4; r++) acc[i][j][r] = 0.f;

    const int iters = K >> 4;           // BK = 16

    if (tid < NSTG) {
        MBAR_INIT(sbase + tid * 8, 256);        // full[tid]: all threads' cp.asyncs
        MBAR_INIT(sbase + 32 + tid * 8, 8);     // empty[tid]: one arrive per warp
    }
    __syncthreads();

    // prefill stages 0..2
    #pragma unroll
    for (int s = 0; s < 3; s++) {
        issue_stage(dbase, s, Ag, Bg, s * 16, lda, ldb, tid);
        cp_arrive(sbase + s * 8);
    }

    for (int it = 0; it < iters; ++it) {
        // 1) produce stage it+3
        const int pn = it + 3;
        if (pn < iters) {
            const int ps = pn & 3;
            if (pn >= NSTG)
                mbar_wait(sbase + 32 + ps * 8, ((pn >> 2) - 1) & 1);
            issue_stage(dbase, ps, Ag, Bg, pn * 16, lda, ldb, tid);
            cp_arrive(sbase + ps * 8);
        }

        // 2) wait for stage it
        const int slot = it & 3;
        mbar_wait(sbase + slot * 8, (it >> 2) & 1);

        const uint32_t aBase = dbase + (uint32_t)(slot * STG_F) * 4u;   // A [128][20]
        const uint32_t bBase = aBase + 2560u * 4u;                      // B [128][20]

        // 3) compute: 2 k-steps, frags via ldmatrix.x4
        #pragma unroll
        for (int ks = 0; ks < 2; ++ks) {
            const int k0 = ks * 8;
            unsigned af[4][4], bf[4][2];
            #pragma unroll
            for (int mt = 0; mt < 4; mt++) {
                uint32_t addr = aBase +
                    (uint32_t)(((wm * 64 + mt * 16 + a_ro) * 20) + k0 + a_co) * 4u;
                ldsm4(af[mt][0], af[mt][1], af[mt][2], af[mt][3], addr);
            }
            #pragma unroll
            for (int np = 0; np < 2; np++) {
                uint32_t addr = bBase +
                    (uint32_t)(((wn * 32 + np * 16 + b_ro) * 20) + k0 + b_co) * 4u;
                ldsm4(bf[2*np][0], bf[2*np][1], bf[2*np+1][0], bf[2*np+1][1], addr);
            }
            #pragma unroll
            for (int mt = 0; mt < 4; mt++)
                #pragma unroll
                for (int nt = 0; nt < 4; nt++)
                    mma_tf32(acc[mt][nt], af[mt], bf[nt]);
        }

        // 4) stage consumed -> warp-level release (lane 0; warp converged)
        if (lane == 0) mbar_arrive(sbase + 32 + slot * 8);
    }

    // epilogue
    #pragma unroll
    for (int mt = 0; mt < 4; mt++) {
        const int row = bm + wm * 64 + mt * 16 + g;
        #pragma unroll
        for (int nt = 0; nt < 4; nt++) {
            const int col = bn + wn * 32 + nt * 8 + 2 * t;
            float2 v0 = make_float2(acc[mt][nt][0], acc[mt][nt][1]);
            float2 v1 = make_float2(acc[mt][nt][2], acc[mt][nt][3]);
            *(float2*)(C + (long)row * ldc + col)       = v0;
            *(float2*)(C + (long)(row + 8) * ldc + col) = v1;
        }
    }
    if (sym && bm != bn) {
        // mirror tile: S[col][row] = S[row][col] (scalar fire-and-forget)
        #pragma unroll
        for (int mt = 0; mt < 4; mt++) {
            const int row = bm + wm * 64 + mt * 16 + g;
            #pragma unroll
            for (int nt = 0; nt < 4; nt++) {
                const int col = bn + wn * 32 + nt * 8 + 2 * t;
                C[(long)col * ldc + row]           = acc[mt][nt][0];
                C[(long)(col + 1) * ldc + row]     = acc[mt][nt][1];
                C[(long)col * ldc + row + 8]       = acc[mt][nt][2];
                C[(long)(col + 1) * ldc + row + 8] = acc[mt][nt][3];
            }
        }
    }
}

// ---------------------------------------------------------------------------
// Depthwise conv (kernel 3, pad 1 along last axis) + bias; output tf32-rounded
// ---------------------------------------------------------------------------
__global__ __launch_bounds__(256)
void conv_bias(const float* __restrict__ y, const float* __restrict__ wc,
               const float* __restrict__ bias, float* __restrict__ p)
{
    long idx = (long)blockIdx.x * blockDim.x + threadIdx.x;   // 8M elems
    if (idx >= (long)BC * NB * NB) return;
    int o = (int)(idx & (NB - 1));
    int c = (int)((idx >> 20) & 3);
    float w0 = wc[c*3+0], w1 = wc[c*3+1], w2 = wc[c*3+2];
    float mid = y[idx];
    float lft = (o > 0)      ? y[idx - 1] : 0.f;
    float rgt = (o < NB - 1) ? y[idx + 1] : 0.f;
    p[idx] = rtf(fmaf(lft, w0, fmaf(mid, w1, fmaf(rgt, w2, bias[c]))));
}

// ---------------------------------------------------------------------------
// RoPE + transpose: Q[bcn][s][d] from p[bc][n*128+d][s]; output tf32-rounded
// ---------------------------------------------------------------------------
__global__ __launch_bounds__(256)
void rope_build(const float* __restrict__ p, float* __restrict__ Q)
{
    long idx = (long)blockIdx.x * blockDim.x + threadIdx.x;   // 4M
    if (idx >= (long)BCN * 64 * NB) return;
    int s   = (int)(idx & (NB - 1));
    int j   = (int)((idx >> 10) & 63);
    int bcn = (int)(idx >> 16);
    int bc = bcn >> 3, n = bcn & 7;

    const float* src = p + ((long)bc * NB + n * HD) * NB + s;
    float*       dst = Q + (long)bcn * (NB * HD) + (long)s * HD;

    if (j < 32) {
        float t0 = src[(2*j + 0) * NB];
        float t1 = src[(2*j + 1) * NB];
        float invf = powf(10000.f, -(float)(2*j) / (float)ROT);
        float ang = (float)s * invf;
        float cs = cosf(ang), sn = sinf(ang);
        dst[2*j + 0] = rtf(t0 * cs - t1 * sn);
        dst[2*j + 1] = rtf(t1 * cs + t0 * sn);
    } else {
        int d = ROT + (j - 32) * 2;
        dst[d + 0] = src[(d + 0) * NB];
        dst[d + 1] = src[(d + 1) * NB];
    }
}

// ---------------------------------------------------------------------------
// Row softmax with scale (one block per row of 1024); float4 I/O; tf32 out
// ---------------------------------------------------------------------------
__global__ __launch_bounds__(256)
void softmax_rows(float* __restrict__ S, float scale)
{
    float4* row4 = (float4*)(S + (long)blockIdx.x * NB);
    const int t = threadIdx.x;
    __shared__ float red[32];

    float4 v = row4[t];
    v.x *= scale; v.y *= scale; v.z *= scale; v.w *= scale;
    float m = fmaxf(fmaxf(v.x, v.y), fmaxf(v.z, v.w));
    #pragma unroll
    for (int o = 16; o > 0; o >>= 1) m = fmaxf(m, __shfl_xor_sync(~0u, m, o));
    if ((t & 31) == 0) red[t >> 5] = m;
    __syncthreads();
    if (t < 32) {
        float x = red[t & 7];
        #pragma unroll
        for (int o = 4; o > 0; o >>= 1) x = fmaxf(x, __shfl_xor_sync(~0u, x, o));
        red[t] = x;
    }
    __syncthreads();
    m = red[0];

    v.x = __expf(v.x - m); v.y = __expf(v.y - m);
    v.z = __expf(v.z - m); v.w = __expf(v.w - m);
    float sum = v.x + v.y + v.z + v.w;
    #pragma unroll
    for (int o = 16; o > 0; o >>= 1) sum += __shfl_xor_sync(~0u, sum, o);
    __syncthreads();
    if ((t & 31) == 0) red[t >> 5] = sum;
    __syncthreads();
    if (t < 32) {
        float x = red[t & 7];
        #pragma unroll
        for (int o = 4; o > 0; o >>= 1) x += __shfl_xor_sync(~0u, x, o);
        red[t] = x;
    }
    __syncthreads();
    float inv = 1.f / red[0];
    v.x = rtf(v.x * inv); v.y = rtf(v.y * inv);
    v.z = rtf(v.z * inv); v.w = rtf(v.w * inv);
    row4[t] = v;
}

// ---------------------------------------------------------------------------
// Merge heads: a_m[bc][n*128+d][s] = av[bcn][s][d]; output tf32-rounded
// ---------------------------------------------------------------------------
__global__ __launch_bounds__(256)
void merge_heads(const float* __restrict__ av, float* __restrict__ am)
{
    __shared__ float tile[32][33];
    int bcn = blockIdx.z;
    const float* src = av + (long)bcn * (NB * HD);
    float*       dst = am + (long)bcn * (NB * HD);
    int d0 = blockIdx.x * 32, s0 = blockIdx.y * 32;
    int tx = threadIdx.x, ty = threadIdx.y;
    #pragma unroll
    for (int i = 0; i < 32; i += 8)
        tile[ty + i][tx] = src[(long)(s0 + ty + i) * HD + d0 + tx];
    __syncthreads();
    #pragma unroll
    for (int i = 0; i < 32; i += 8)
        dst[(long)(d0 + ty + i) * NB + s0 + tx] = rtf(tile[tx][ty + i]);
}

// ---------------------------------------------------------------------------
// Launch
// ---------------------------------------------------------------------------
extern "C" void kernel_launch(void* const* d_in, const int* in_sizes, int n_in,
                              void* d_out, int out_size)
{
    const float* x      = (const float*)d_in[0];  // (2,4,1024,1024)
    const float* w_lin  = (const float*)d_in[1];  // (4,1024,1024)
    const float* w_conv = (const float*)d_in[2];  // (4,1,1,3)
    const float* b_conv = (const float*)d_in[3];  // (4,)
    const float* w_out  = (const float*)d_in[4];  // (4,1024,1024)
    float* out = (float*)d_out;

    float *y, *p, *q, *s, *av, *am, *xc, *wl, *wo;
    cudaGetSymbolAddress((void**)&y,  g_y);
    cudaGetSymbolAddress((void**)&p,  g_p);
    cudaGetSymbolAddress((void**)&q,  g_q);
    cudaGetSymbolAddress((void**)&s,  g_s);
    cudaGetSymbolAddress((void**)&av, g_av);
    cudaGetSymbolAddress((void**)&am, g_am);
    cudaGetSymbolAddress((void**)&xc, g_xc);
    cudaGetSymbolAddress((void**)&wl, g_wl);
    cudaGetSymbolAddress((void**)&wo, g_wo);

    cudaFuncSetAttribute(gemm_tc, cudaFuncAttributeMaxDynamicSharedMemorySize, GEMM_SMEM);

    const long MM = (long)NB * NB;          // 1048576
    const long QS = (long)NB * HD;          // 131072

    // 0) pre-round GEMM inputs to tf32
    cvt_tf32<<<(int)(BC * MM / 4 / 256), 256>>>(x, xc, (int)(BC * MM / 4));
    cvt_tf32<<<(int)(CH * MM / 4 / 256), 256>>>(w_lin, wl, (int)(CH * MM / 4));
    cvt_tf32<<<(int)(CH * MM / 4 / 256), 256>>>(w_out, wo, (int)(CH * MM / 4));

    // 1) proj GEMM: y[bc] = x[bc] @ w_lin[c]^T
    gemm_tc<<<dim3(8, 8, BC), 256, GEMM_SMEM>>>(xc, wl, y,
        NB, NB, NB, NB, MM, MM, MM, CH, 0);

    // 2) depthwise conv3 + bias (writes tf32 p)
    conv_bias<<<(int)((BC * MM + 255) / 256), 256>>>(y, w_conv, b_conv, p);

    // 3) RoPE -> Q (== K), tf32
    rope_build<<<(int)(((long)BCN * 64 * NB + 255) / 256), 256>>>(p, q);

    // 4) scores = Q @ Q^T: symmetric -> upper-triangle tiles only + mirror
    gemm_tc<<<dim3(8, 8, BCN), 256, GEMM_SMEM>>>(q, q, s,
        HD, HD, HD, NB, QS, QS, MM, BCN, 1);

    // 5) softmax rows, scale = 1/sqrt(1024), writes tf32 probs
    softmax_rows<<<BCN * NB, 256>>>(s, 1.0f / 32.0f);

    // 6) av = P @ V   (V^T is the p slice: stride 131072 per bcn, ldb=1024)
    gemm_tc<<<dim3(1, 8, BCN), 256, GEMM_SMEM>>>(s, p, av,
        NB, NB, NB, HD, MM, QS, QS, BCN, 0);

    // 7) merge heads (batched transpose), writes tf32 am
    merge_heads<<<dim3(4, 32, BCN), dim3(32, 8)>>>(av, am);

    // 8) out GEMM: out[bc] = am[bc] @ w_out[c]^T
    gemm_tc<<<dim3(8, 8, BC), 256, GEMM_SMEM>>>(am, wo, out,
        NB, NB, NB, NB, MM, MM, MM, CH, 0);
}

// round 16
// speedup vs baseline: 1.8028x; 1.4355x over previous
#include <cuda_runtime.h>
#include <cuda_fp16.h>
#include <math.h>
#include <stdint.h>

// ---------------------------------------------------------------------------
// Problem constants: x(2,4,1024,1024), HEADS=8, D=128, ROT_DIM=64
// ---------------------------------------------------------------------------
#define BATCH   2
#define CH      4
#define BC      (BATCH*CH)        // 8
#define NB      1024              // BINS
#define NH      8                 // heads
#define HD      128               // head dim
#define BCN     (BC*NH)           // 64
#define ROT     64                // rotary dims

// Scratch (static __device__ — no allocations allowed). All fp16 now.
__device__ __half g_y [BC  * NB * NB];   // proj gemm out (pre-conv)     16MB
__device__ __half g_p [BC  * NB * NB];   // conv+bias out (also V^T)     16MB
__device__ __half g_q [BCN * NB * HD];   // roped Q (= K)                16MB
__device__ __half g_s [BCN * NB * NB];   // scores -> probs             128MB
__device__ __half g_av[BCN * NB * HD];   // softmax @ V                  16MB
__device__ __half g_am[BC  * NB * NB];   // merged heads                 16MB
__device__ __half g_xc[BC  * NB * NB];   // x in fp16                    16MB
__device__ __half g_wl[CH  * NB * NB];   // w_lin fp16                    8MB
__device__ __half g_wo[CH  * NB * NB];   // w_out fp16                    8MB

// ---------------------------------------------------------------------------
// helpers
// ---------------------------------------------------------------------------
__device__ __forceinline__ uint32_t smem_u32(const void* p) {
    uint32_t a;
    asm("{ .reg .u64 t; cvta.to.shared.u64 t, %1; cvt.u32.u64 %0, t; }"
        : "=r"(a) : "l"(p));
    return a;
}

__device__ __forceinline__ void cp16(uint32_t dst, const void* src) {
    asm volatile("cp.async.ca.shared.global [%0], [%1], 16;" :: "r"(dst), "l"(src));
}

// cp.async arrive-on-mbarrier, NOINC (plain form is inc-then-arrive -> deadlock)
__device__ __forceinline__ void cp_arrive(uint32_t mbar) {
    asm volatile("cp.async.mbarrier.arrive.noinc.shared.b64 [%0];" :: "r"(mbar) : "memory");
}

#define MBAR_INIT(addr, cnt) \
    asm volatile("mbarrier.init.shared.b64 [%0], %1;" :: "r"(addr), "r"(cnt) : "memory")

__device__ __forceinline__ void mbar_arrive(uint32_t addr) {
    asm volatile("mbarrier.arrive.shared.b64 _, [%0];" :: "r"(addr) : "memory");
}

__device__ __forceinline__ void mbar_wait(uint32_t addr, uint32_t parity) {
    asm volatile(
        "{\n\t.reg .pred P1;\n\t"
        "WL_%=:\n\t"
        "mbarrier.try_wait.parity.acquire.cta.shared::cta.b64 P1, [%0], %1, 0x989680;\n\t"
        "@P1 bra.uni WD_%=;\n\t"
        "bra.uni WL_%=;\n\t"
        "WD_%=:\n\t}"
        :: "r"(addr), "r"(parity) : "memory");
}

__device__ __forceinline__ void ldsm4(unsigned& r0, unsigned& r1, unsigned& r2,
                                      unsigned& r3, uint32_t addr) {
    asm volatile("ldmatrix.sync.aligned.m8n8.x4.shared.b16 {%0,%1,%2,%3}, [%4];"
                 : "=r"(r0), "=r"(r1), "=r"(r2), "=r"(r3) : "r"(addr));
}

// fp16 MMA, fp32 accumulate: m16n8k16
__device__ __forceinline__ void mma_f16(float* d, const unsigned* a, const unsigned* b) {
    asm volatile(
        "mma.sync.aligned.m16n8k16.row.col.f32.f16.f16.f32 "
        "{%0,%1,%2,%3}, {%4,%5,%6,%7}, {%8,%9}, {%0,%1,%2,%3};"
        : "+f"(d[0]), "+f"(d[1]), "+f"(d[2]), "+f"(d[3])
        : "r"(a[0]), "r"(a[1]), "r"(a[2]), "r"(a[3]), "r"(b[0]), "r"(b[1]));
}

// ---------------------------------------------------------------------------
// float -> fp16 conversion pass (for x, w_lin, w_out)
// ---------------------------------------------------------------------------
__global__ __launch_bounds__(256)
void cvt_f2h(const float* __restrict__ in, __half* __restrict__ out, int n4)
{
    int i = blockIdx.x * 256 + threadIdx.x;
    if (i >= n4) return;
    float4 v = ((const float4*)in)[i];
    __half2 h0 = __floats2half2_rn(v.x, v.y);
    __half2 h1 = __floats2half2_rn(v.z, v.w);
    ((__half2*)out)[2*i]   = h0;
    ((__half2*)out)[2*i+1] = h1;
}

// ---------------------------------------------------------------------------
// Batched NT GEMM, fp16 inputs, fp32 accumulate (same precision as tf32!):
//   C[m,n] = sum_k A[m*lda+k] * B[n*ldb+k]      (lda/ldb/strides in halfs)
// 256 threads (8 warps, 2x4), block 128x128, warp tile 64x32, m16n8k16:
// per k16 step: 6 ldmatrix.x4 + 16 MMA — double the FLOPs of the tf32
// m16n8k8 version at the SAME instruction/crossbar cost.
// BK=32, 4 smem slots, per-stage mbarrier pipeline (R11/R15 champion design:
// full[s] 256 cp.async-noinc arrivals, empty[s] 8 warp arrivals).
// Stage rows: 32 halfs data, stride 40 halfs (80B): bank walk 20r mod 32
// covers all 32 banks -> ldmatrix conflict-free.
// sym!=0 => symmetric C: bn<bm CTAs exit; off-diag tiles mirror (scalar).
// outHalf: 1 -> store __half C, 0 -> store fp32 C (final output).
// __launch_bounds__(256,2): 2 CTAs/SM; smem ~80KB/CTA.
// ---------------------------------------------------------------------------
#define STG_H 10240         // halfs per stage (2 * 128 * 40)
#define NSTG  4
#define GEMM_SMEM (64 + NSTG * STG_H * 2)   // 64B barriers + 80KB stages

__device__ __forceinline__ void issue_stage(uint32_t dbase, int slot,
    const __half* Ag, const __half* Bg, int kbase, int lda, int ldb, int tid)
{
    const int r  = tid >> 1;            // 0..127
    const int c0 = (tid & 1) * 16;      // half offset 0 or 16
    uint32_t a_off = dbase + (uint32_t)(slot * STG_H + r * 40 + c0) * 2u;
    uint32_t b_off = a_off + 5120u * 2u;
    const __half* ap = Ag + (long)r * lda + kbase + c0;
    const __half* bp = Bg + (long)r * ldb + kbase + c0;
    cp16(a_off,      ap);
    cp16(a_off + 16, ap + 8);
    cp16(b_off,      bp);
    cp16(b_off + 16, bp + 8);
}

__global__ __launch_bounds__(256, 2)
void gemm_tc(const __half* __restrict__ A, const __half* __restrict__ B,
             void* __restrict__ Cv,
             int K, int lda, int ldb, int ldc,
             long sA, long sB, long sC, int modB, int sym, int outHalf)
{
    const int bm = blockIdx.y * 128;
    const int bn = blockIdx.x * 128;
    if (sym && bn < bm) return;          // symmetric: upper triangle only

    extern __shared__ char smc[];
    const uint32_t sbase = smem_u32(smc);    // barriers: full[4] @0, empty[4] @32
    const uint32_t dbase = sbase + 64;       // stage data

    const int tid = threadIdx.x;
    const int batch = blockIdx.z;

    const __half* Ag = A + (long)batch * sA + (long)bm * lda;
    const __half* Bg = B + (long)(batch % modB) * sB + (long)bn * ldb;

    const int wid  = tid >> 5;
    const int lane = tid & 31;
    const int wm = wid & 1;             // 0..1 (64 rows)
    const int wn = wid >> 1;            // 0..3 (32 cols)
    const int g = lane >> 2;            // 0..7
    const int t = lane & 3;             // 0..3

    // ldmatrix per-lane address components (same proven pattern, b16 scale):
    // A mats: (m0-7,klo),(m8-15,klo),(m0-7,khi),(m8-15,khi) -> a-frag order
    const int a_ro = (lane & 7) + ((lane >> 3) & 1) * 8;   // 0..15
    const int a_co = (lane >> 4) * 8;                      // half off 0 or 8
    // B mats: (n0-7,klo),(n0-7,khi),(n8-15,klo),(n8-15,khi) -> b-frag order
    const int b_ro = (lane & 7) + (lane >> 4) * 8;         // 0..15
    const int b_co = ((lane >> 3) & 1) * 8;                // half off 0 or 8

    float acc[4][4][4];
    #pragma unroll
    for (int i = 0; i < 4; i++)
        #pragma unroll
        for (int j = 0; j < 4; j++)
            #pragma unroll
            for (int r = 0; r < 4; r++) acc[i][j][r] = 0.f;

    const int iters = K >> 5;           // BK = 32

    if (tid < NSTG) {
        MBAR_INIT(sbase + tid * 8, 256);        // full[tid]
        MBAR_INIT(sbase + 32 + tid * 8, 8);     // empty[tid]: one per warp
    }
    __syncthreads();

    // prefill stages 0..2
    #pragma unroll
    for (int s = 0; s < 3; s++) {
        if (s < iters) {
            issue_stage(dbase, s, Ag, Bg, s * 32, lda, ldb, tid);
            cp_arrive(sbase + s * 8);
        }
    }

    for (int it = 0; it < iters; ++it) {
        // 1) produce stage it+3
        const int pn = it + 3;
        if (pn < iters) {
            const int ps = pn & 3;
            if (pn >= NSTG)
                mbar_wait(sbase + 32 + ps * 8, ((pn >> 2) - 1) & 1);
            issue_stage(dbase, ps, Ag, Bg, pn * 32, lda, ldb, tid);
            cp_arrive(sbase + ps * 8);
        }

        // 2) wait for stage it
        const int slot = it & 3;
        mbar_wait(sbase + slot * 8, (it >> 2) & 1);

        const uint32_t aBase = dbase + (uint32_t)(slot * STG_H) * 2u;   // A [128][40h]
        const uint32_t bBase = aBase + 5120u * 2u;                      // B [128][40h]

        // 3) compute: 2 k16-steps, frags via ldmatrix.x4
        #pragma unroll
        for (int ks = 0; ks < 2; ++ks) {
            const int k0 = ks * 16;
            unsigned af[4][4], bf[4][2];
            #pragma unroll
            for (int mt = 0; mt < 4; mt++) {
                uint32_t addr = aBase +
                    (uint32_t)(((wm * 64 + mt * 16 + a_ro) * 40) + k0 + a_co) * 2u;
                ldsm4(af[mt][0], af[mt][1], af[mt][2], af[mt][3], addr);
            }
            #pragma unroll
            for (int np = 0; np < 2; np++) {
                uint32_t addr = bBase +
                    (uint32_t)(((wn * 32 + np * 16 + b_ro) * 40) + k0 + b_co) * 2u;
                ldsm4(bf[2*np][0], bf[2*np][1], bf[2*np+1][0], bf[2*np+1][1], addr);
            }
            #pragma unroll
            for (int mt = 0; mt < 4; mt++)
                #pragma unroll
                for (int nt = 0; nt < 4; nt++)
                    mma_f16(acc[mt][nt], af[mt], bf[nt]);
        }

        // 4) stage consumed -> warp-level release (lane 0; warp converged)
        if (lane == 0) mbar_arrive(sbase + 32 + slot * 8);
    }

    // epilogue
    if (outHalf) {
        __half* C = (__half*)Cv + (long)batch * sC;
        #pragma unroll
        for (int mt = 0; mt < 4; mt++) {
            const int row = bm + wm * 64 + mt * 16 + g;
            #pragma unroll
            for (int nt = 0; nt < 4; nt++) {
                const int col = bn + wn * 32 + nt * 8 + 2 * t;
                *(__half2*)(C + (long)row * ldc + col) =
                    __floats2half2_rn(acc[mt][nt][0], acc[mt][nt][1]);
                *(__half2*)(C + (long)(row + 8) * ldc + col) =
                    __floats2half2_rn(acc[mt][nt][2], acc[mt][nt][3]);
            }
        }
        if (sym && bm != bn) {
            #pragma unroll
            for (int mt = 0; mt < 4; mt++) {
                const int row = bm + wm * 64 + mt * 16 + g;
                #pragma unroll
                for (int nt = 0; nt < 4; nt++) {
                    const int col = bn + wn * 32 + nt * 8 + 2 * t;
                    C[(long)col * ldc + row]           = __float2half(acc[mt][nt][0]);
                    C[(long)(col + 1) * ldc + row]     = __float2half(acc[mt][nt][1]);
                    C[(long)col * ldc + row + 8]       = __float2half(acc[mt][nt][2]);
                    C[(long)(col + 1) * ldc + row + 8] = __float2half(acc[mt][nt][3]);
                }
            }
        }
    } else {
        float* C = (float*)Cv + (long)batch * sC;
        #pragma unroll
        for (int mt = 0; mt < 4; mt++) {
            const int row = bm + wm * 64 + mt * 16 + g;
            #pragma unroll
            for (int nt = 0; nt < 4; nt++) {
                const int col = bn + wn * 32 + nt * 8 + 2 * t;
                *(float2*)(C + (long)row * ldc + col) =
                    make_float2(acc[mt][nt][0], acc[mt][nt][1]);
                *(float2*)(C + (long)(row + 8) * ldc + col) =
                    make_float2(acc[mt][nt][2], acc[mt][nt][3]);
            }
        }
    }
}

// ---------------------------------------------------------------------------
// Depthwise conv (kernel 3, pad 1 along last axis) + bias; fp16 in/out
// ---------------------------------------------------------------------------
__global__ __launch_bounds__(256)
void conv_bias(const __half* __restrict__ y, const float* __restrict__ wc,
               const float* __restrict__ bias, __half* __restrict__ p)
{
    long idx = (long)blockIdx.x * blockDim.x + threadIdx.x;   // 8M elems
    if (idx >= (long)BC * NB * NB) return;
    int o = (int)(idx & (NB - 1));
    int c = (int)((idx >> 20) & 3);
    float w0 = wc[c*3+0], w1 = wc[c*3+1], w2 = wc[c*3+2];
    float mid = __half2float(y[idx]);
    float lft = (o > 0)      ? __half2float(y[idx - 1]) : 0.f;
    float rgt = (o < NB - 1) ? __half2float(y[idx + 1]) : 0.f;
    p[idx] = __float2half(fmaf(lft, w0, fmaf(mid, w1, fmaf(rgt, w2, bias[c]))));
}

// ---------------------------------------------------------------------------
// RoPE + transpose: Q[bcn][s][d] from p[bc][n*128+d][s]; fp16 in/out
// ---------------------------------------------------------------------------
__global__ __launch_bounds__(256)
void rope_build(const __half* __restrict__ p, __half* __restrict__ Q)
{
    long idx = (long)blockIdx.x * blockDim.x + threadIdx.x;   // 4M
    if (idx >= (long)BCN * 64 * NB) return;
    int s   = (int)(idx & (NB - 1));
    int j   = (int)((idx >> 10) & 63);
    int bcn = (int)(idx >> 16);
    int bc = bcn >> 3, n = bcn & 7;

    const __half* src = p + ((long)bc * NB + n * HD) * NB + s;
    __half*       dst = Q + (long)bcn * (NB * HD) + (long)s * HD;

    if (j < 32) {
        float t0 = __half2float(src[(2*j + 0) * NB]);
        float t1 = __half2float(src[(2*j + 1) * NB]);
        float invf = powf(10000.f, -(float)(2*j) / (float)ROT);
        float ang = (float)s * invf;
        float cs = cosf(ang), sn = sinf(ang);
        dst[2*j + 0] = __float2half(t0 * cs - t1 * sn);
        dst[2*j + 1] = __float2half(t1 * cs + t0 * sn);
    } else {
        int d = ROT + (j - 32) * 2;
        dst[d + 0] = src[(d + 0) * NB];
        dst[d + 1] = src[(d + 1) * NB];
    }
}

// ---------------------------------------------------------------------------
// Row softmax with scale (one block per fp16 row of 1024)
// ---------------------------------------------------------------------------
__global__ __launch_bounds__(256)
void softmax_rows(__half* __restrict__ S, float scale)
{
    __half2* row2 = (__half2*)(S + (long)blockIdx.x * NB);   // 512 half2
    const int t = threadIdx.x;
    __shared__ float red[32];

    float2 a = __half22float2(row2[2*t]);
    float2 b = __half22float2(row2[2*t + 1]);
    a.x *= scale; a.y *= scale; b.x *= scale; b.y *= scale;
    float m = fmaxf(fmaxf(a.x, a.y), fmaxf(b.x, b.y));
    #pragma unroll
    for (int o = 16; o > 0; o >>= 1) m = fmaxf(m, __shfl_xor_sync(~0u, m, o));
    if ((t & 31) == 0) red[t >> 5] = m;
    __syncthreads();
    if (t < 32) {
        float x = red[t & 7];
        #pragma unroll
        for (int o = 4; o > 0; o >>= 1) x = fmaxf(x, __shfl_xor_sync(~0u, x, o));
        red[t] = x;
    }
    __syncthreads();
    m = red[0];

    a.x = __expf(a.x - m); a.y = __expf(a.y - m);
    b.x = __expf(b.x - m); b.y = __expf(b.y - m);
    float sum = a.x + a.y + b.x + b.y;
    #pragma unroll
    for (int o = 16; o > 0; o >>= 1) sum += __shfl_xor_sync(~0u, sum, o);
    __syncthreads();
    if ((t & 31) == 0) red[t >> 5] = sum;
    __syncthreads();
    if (t < 32) {
        float x = red[t & 7];
        #pragma unroll
        for (int o = 4; o > 0; o >>= 1) x += __shfl_xor_sync(~0u, x, o);
        red[t] = x;
    }
    __syncthreads();
    float inv = 1.f / red[0];
    row2[2*t]     = __floats2half2_rn(a.x * inv, a.y * inv);
    row2[2*t + 1] = __floats2half2_rn(b.x * inv, b.y * inv);
}

// ---------------------------------------------------------------------------
// Merge heads: a_m[bc][n*128+d][s] = av[bcn][s][d]; fp16 in/out
// ---------------------------------------------------------------------------
__global__ __launch_bounds__(256)
void merge_heads(const __half* __restrict__ av, __half* __restrict__ am)
{
    __shared__ float tile[32][33];
    int bcn = blockIdx.z;
    const __half* src = av + (long)bcn * (NB * HD);
    __half*       dst = am + (long)bcn * (NB * HD);
    int d0 = blockIdx.x * 32, s0 = blockIdx.y * 32;
    int tx = threadIdx.x, ty = threadIdx.y;
    #pragma unroll
    for (int i = 0; i < 32; i += 8)
        tile[ty + i][tx] = __half2float(src[(long)(s0 + ty + i) * HD + d0 + tx]);
    __syncthreads();
    #pragma unroll
    for (int i = 0; i < 32; i += 8)
        dst[(long)(d0 + ty + i) * NB + s0 + tx] = __float2half(tile[tx][ty + i]);
}

// ---------------------------------------------------------------------------
// Launch
// ---------------------------------------------------------------------------
extern "C" void kernel_launch(void* const* d_in, const int* in_sizes, int n_in,
                              void* d_out, int out_size)
{
    const float* x      = (const float*)d_in[0];  // (2,4,1024,1024)
    const float* w_lin  = (const float*)d_in[1];  // (4,1024,1024)
    const float* w_conv = (const float*)d_in[2];  // (4,1,1,3)
    const float* b_conv = (const float*)d_in[3];  // (4,)
    const float* w_out  = (const float*)d_in[4];  // (4,1024,1024)
    float* out = (float*)d_out;

    __half *y, *p, *q, *s, *av, *am, *xc, *wl, *wo;
    cudaGetSymbolAddress((void**)&y,  g_y);
    cudaGetSymbolAddress((void**)&p,  g_p);
    cudaGetSymbolAddress((void**)&q,  g_q);
    cudaGetSymbolAddress((void**)&s,  g_s);
    cudaGetSymbolAddress((void**)&av, g_av);
    cudaGetSymbolAddress((void**)&am, g_am);
    cudaGetSymbolAddress((void**)&xc, g_xc);
    cudaGetSymbolAddress((void**)&wl, g_wl);
    cudaGetSymbolAddress((void**)&wo, g_wo);

    cudaFuncSetAttribute(gemm_tc, cudaFuncAttributeMaxDynamicSharedMemorySize, GEMM_SMEM);

    const long MM = (long)NB * NB;          // 1048576 (elements)
    const long QS = (long)NB * HD;          // 131072

    // 0) convert GEMM inputs to fp16 (same 10-bit mantissa as tf32)
    cvt_f2h<<<(int)(BC * MM / 4 / 256), 256>>>(x, xc, (int)(BC * MM / 4));
    cvt_f2h<<<(int)(CH * MM / 4 / 256), 256>>>(w_lin, wl, (int)(CH * MM / 4));
    cvt_f2h<<<(int)(CH * MM / 4 / 256), 256>>>(w_out, wo, (int)(CH * MM / 4));

    // 1) proj GEMM: y[bc] = x[bc] @ w_lin[c]^T   (fp16 out)
    gemm_tc<<<dim3(8, 8, BC), 256, GEMM_SMEM>>>(xc, wl, y,
        NB, NB, NB, NB, MM, MM, MM, CH, 0, 1);

    // 2) depthwise conv3 + bias (fp16 p)
    conv_bias<<<(int)((BC * MM + 255) / 256), 256>>>(y, w_conv, b_conv, p);

    // 3) RoPE -> Q (== K), fp16
    rope_build<<<(int)(((long)BCN * 64 * NB + 255) / 256), 256>>>(p, q);

    // 4) scores = Q @ Q^T: symmetric -> upper-triangle tiles only + mirror
    gemm_tc<<<dim3(8, 8, BCN), 256, GEMM_SMEM>>>(q, q, s,
        HD, HD, HD, NB, QS, QS, MM, BCN, 1, 1);

    // 5) softmax rows, scale = 1/sqrt(1024), fp16 probs
    softmax_rows<<<BCN * NB, 256>>>(s, 1.0f / 32.0f);

    // 6) av = P @ V   (V^T is the p slice: stride 131072 halfs per bcn)
    gemm_tc<<<dim3(1, 8, BCN), 256, GEMM_SMEM>>>(s, p, av,
        NB, NB, NB, HD, MM, QS, QS, BCN, 0, 1);

    // 7) merge heads (batched transpose), fp16
    merge_heads<<<dim3(4, 32, BCN), dim3(32, 8)>>>(av, am);

    // 8) out GEMM: out[bc] = am[bc] @ w_out[c]^T  (fp32 final output)
    gemm_tc<<<dim3(8, 8, BC), 256, GEMM_SMEM>>>(am, wo, out,
        NB, NB, NB, NB, MM, MM, MM, CH, 0, 0);
}

// round 17
// speedup vs baseline: 1.8389x; 1.0201x over previous
#include <cuda_runtime.h>
#include <cuda_fp16.h>
#include <math.h>
#include <stdint.h>

// ---------------------------------------------------------------------------
// Problem constants: x(2,4,1024,1024), HEADS=8, D=128, ROT_DIM=64
// ---------------------------------------------------------------------------
#define BATCH   2
#define CH      4
#define BC      (BATCH*CH)        // 8
#define NB      1024              // BINS
#define NH      8                 // heads
#define HD      128               // head dim
#define BCN     (BC*NH)           // 64
#define ROT     64                // rotary dims

// Scratch (static __device__ — no allocations allowed). All fp16.
__device__ __half g_y [BC  * NB * NB];   // proj gemm out (pre-conv)     16MB
__device__ __half g_p [BC  * NB * NB];   // conv+bias out (also V^T)     16MB
__device__ __half g_q [BCN * NB * HD];   // roped Q (= K)                16MB
__device__ __half g_s [BCN * NB * NB];   // scores -> probs             128MB
__device__ __half g_am[BC  * NB * NB];   // merged heads (AV^T direct)   16MB
__device__ __half g_xc[BC  * NB * NB];   // x in fp16                    16MB
__device__ __half g_wl[CH  * NB * NB];   // w_lin fp16                    8MB
__device__ __half g_wo[CH  * NB * NB];   // w_out fp16                    8MB

// ---------------------------------------------------------------------------
// helpers
// ---------------------------------------------------------------------------
__device__ __forceinline__ uint32_t smem_u32(const void* p) {
    uint32_t a;
    asm("{ .reg .u64 t; cvta.to.shared.u64 t, %1; cvt.u32.u64 %0, t; }"
        : "=r"(a) : "l"(p));
    return a;
}

__device__ __forceinline__ void cp16(uint32_t dst, const void* src) {
    asm volatile("cp.async.ca.shared.global [%0], [%1], 16;" :: "r"(dst), "l"(src));
}

// cp.async arrive-on-mbarrier, NOINC (plain form is inc-then-arrive -> deadlock)
__device__ __forceinline__ void cp_arrive(uint32_t mbar) {
    asm volatile("cp.async.mbarrier.arrive.noinc.shared.b64 [%0];" :: "r"(mbar) : "memory");
}

#define MBAR_INIT(addr, cnt) \
    asm volatile("mbarrier.init.shared.b64 [%0], %1;" :: "r"(addr), "r"(cnt) : "memory")

__device__ __forceinline__ void mbar_arrive(uint32_t addr) {
    asm volatile("mbarrier.arrive.shared.b64 _, [%0];" :: "r"(addr) : "memory");
}

__device__ __forceinline__ void mbar_wait(uint32_t addr, uint32_t parity) {
    asm volatile(
        "{\n\t.reg .pred P1;\n\t"
        "WL_%=:\n\t"
        "mbarrier.try_wait.parity.acquire.cta.shared::cta.b64 P1, [%0], %1, 0x989680;\n\t"
        "@P1 bra.uni WD_%=;\n\t"
        "bra.uni WL_%=;\n\t"
        "WD_%=:\n\t}"
        :: "r"(addr), "r"(parity) : "memory");
}

__device__ __forceinline__ void ldsm4(unsigned& r0, unsigned& r1, unsigned& r2,
                                      unsigned& r3, uint32_t addr) {
    asm volatile("ldmatrix.sync.aligned.m8n8.x4.shared.b16 {%0,%1,%2,%3}, [%4];"
                 : "=r"(r0), "=r"(r1), "=r"(r2), "=r"(r3) : "r"(addr));
}

// fp16 MMA, fp32 accumulate: m16n8k16
__device__ __forceinline__ void mma_f16(float* d, const unsigned* a, const unsigned* b) {
    asm volatile(
        "mma.sync.aligned.m16n8k16.row.col.f32.f16.f16.f32 "
        "{%0,%1,%2,%3}, {%4,%5,%6,%7}, {%8,%9}, {%0,%1,%2,%3};"
        : "+f"(d[0]), "+f"(d[1]), "+f"(d[2]), "+f"(d[3])
        : "r"(a[0]), "r"(a[1]), "r"(a[2]), "r"(a[3]), "r"(b[0]), "r"(b[1]));
}

// ---------------------------------------------------------------------------
// float -> fp16 conversion pass (for x, w_lin, w_out)
// ---------------------------------------------------------------------------
__global__ __launch_bounds__(256)
void cvt_f2h(const float* __restrict__ in, __half* __restrict__ out, int n4)
{
    int i = blockIdx.x * 256 + threadIdx.x;
    if (i >= n4) return;
    float4 v = ((const float4*)in)[i];
    ((__half2*)out)[2*i]   = __floats2half2_rn(v.x, v.y);
    ((__half2*)out)[2*i+1] = __floats2half2_rn(v.z, v.w);
}

// ---------------------------------------------------------------------------
// Batched NT GEMM, fp16 inputs, fp32 accumulate:
//   C[m,n] = sum_k A[m*lda+k] * B[n*ldb+k]      (lda/ldb/strides in halfs)
// 256 threads (8 warps, 2x4), block 128x128, warp tile 64x32, m16n8k16.
// BK=32, 4 smem slots, per-stage mbarrier pipeline (champion design:
// full[s] 256 cp.async-noinc arrivals, empty[s] 8 warp arrivals).
// Stage rows: 32 halfs data, stride 40 halfs (80B) -> ldmatrix conflict-free.
// sym!=0 => symmetric C: bn<bm CTAs exit; off-diag tiles mirror (scalar).
// outHalf: 1 -> __half C, 0 -> fp32 C (final output).
// __launch_bounds__(256,2): 2 CTAs/SM; smem ~80KB/CTA.
// ---------------------------------------------------------------------------
#define STG_H 10240         // halfs per stage (2 * 128 * 40)
#define NSTG  4
#define GEMM_SMEM (64 + NSTG * STG_H * 2)   // 64B barriers + 80KB stages

__device__ __forceinline__ void issue_stage(uint32_t dbase, int slot,
    const __half* Ag, const __half* Bg, int kbase, int lda, int ldb, int tid)
{
    const int r  = tid >> 1;            // 0..127
    const int c0 = (tid & 1) * 16;      // half offset 0 or 16
    uint32_t a_off = dbase + (uint32_t)(slot * STG_H + r * 40 + c0) * 2u;
    uint32_t b_off = a_off + 5120u * 2u;
    const __half* ap = Ag + (long)r * lda + kbase + c0;
    const __half* bp = Bg + (long)r * ldb + kbase + c0;
    cp16(a_off,      ap);
    cp16(a_off + 16, ap + 8);
    cp16(b_off,      bp);
    cp16(b_off + 16, bp + 8);
}

__global__ __launch_bounds__(256, 2)
void gemm_tc(const __half* __restrict__ A, const __half* __restrict__ B,
             void* __restrict__ Cv,
             int K, int lda, int ldb, int ldc,
             long sA, long sB, long sC, int modB, int sym, int outHalf)
{
    const int bm = blockIdx.y * 128;
    const int bn = blockIdx.x * 128;
    if (sym && bn < bm) return;          // symmetric: upper triangle only

    extern __shared__ char smc[];
    const uint32_t sbase = smem_u32(smc);    // barriers: full[4] @0, empty[4] @32
    const uint32_t dbase = sbase + 64;       // stage data

    const int tid = threadIdx.x;
    const int batch = blockIdx.z;

    const __half* Ag = A + (long)batch * sA + (long)bm * lda;
    const __half* Bg = B + (long)(batch % modB) * sB + (long)bn * ldb;

    const int wid  = tid >> 5;
    const int lane = tid & 31;
    const int wm = wid & 1;             // 0..1 (64 rows)
    const int wn = wid >> 1;            // 0..3 (32 cols)
    const int g = lane >> 2;            // 0..7
    const int t = lane & 3;             // 0..3

    // ldmatrix per-lane address components
    const int a_ro = (lane & 7) + ((lane >> 3) & 1) * 8;   // 0..15
    const int a_co = (lane >> 4) * 8;                      // half off 0 or 8
    const int b_ro = (lane & 7) + (lane >> 4) * 8;         // 0..15
    const int b_co = ((lane >> 3) & 1) * 8;                // half off 0 or 8

    float acc[4][4][4];
    #pragma unroll
    for (int i = 0; i < 4; i++)
        #pragma unroll
        for (int j = 0; j < 4; j++)
            #pragma unroll
            for (int r = 0; r < 4; r++) acc[i][j][r] = 0.f;

    const int iters = K >> 5;           // BK = 32

    if (tid < NSTG) {
        MBAR_INIT(sbase + tid * 8, 256);        // full[tid]
        MBAR_INIT(sbase + 32 + tid * 8, 8);     // empty[tid]: one per warp
    }
    __syncthreads();

    // prefill stages 0..2
    #pragma unroll
    for (int s = 0; s < 3; s++) {
        if (s < iters) {
            issue_stage(dbase, s, Ag, Bg, s * 32, lda, ldb, tid);
            cp_arrive(sbase + s * 8);
        }
    }

    for (int it = 0; it < iters; ++it) {
        // 1) produce stage it+3
        const int pn = it + 3;
        if (pn < iters) {
            const int ps = pn & 3;
            if (pn >= NSTG)
                mbar_wait(sbase + 32 + ps * 8, ((pn >> 2) - 1) & 1);
            issue_stage(dbase, ps, Ag, Bg, pn * 32, lda, ldb, tid);
            cp_arrive(sbase + ps * 8);
        }

        // 2) wait for stage it
        const int slot = it & 3;
        mbar_wait(sbase + slot * 8, (it >> 2) & 1);

        const uint32_t aBase = dbase + (uint32_t)(slot * STG_H) * 2u;   // A [128][40h]
        const uint32_t bBase = aBase + 5120u * 2u;                      // B [128][40h]

        // 3) compute: 2 k16-steps, frags via ldmatrix.x4
        #pragma unroll
        for (int ks = 0; ks < 2; ++ks) {
            const int k0 = ks * 16;
            unsigned af[4][4], bf[4][2];
            #pragma unroll
            for (int mt = 0; mt < 4; mt++) {
                uint32_t addr = aBase +
                    (uint32_t)(((wm * 64 + mt * 16 + a_ro) * 40) + k0 + a_co) * 2u;
                ldsm4(af[mt][0], af[mt][1], af[mt][2], af[mt][3], addr);
            }
            #pragma unroll
            for (int np = 0; np < 2; np++) {
                uint32_t addr = bBase +
                    (uint32_t)(((wn * 32 + np * 16 + b_ro) * 40) + k0 + b_co) * 2u;
                ldsm4(bf[2*np][0], bf[2*np][1], bf[2*np+1][0], bf[2*np+1][1], addr);
            }
            #pragma unroll
            for (int mt = 0; mt < 4; mt++)
                #pragma unroll
                for (int nt = 0; nt < 4; nt++)
                    mma_f16(acc[mt][nt], af[mt], bf[nt]);
        }

        // 4) stage consumed -> warp-level release (lane 0; warp converged)
        if (lane == 0) mbar_arrive(sbase + 32 + slot * 8);
    }

    // epilogue
    if (outHalf) {
        __half* C = (__half*)Cv + (long)batch * sC;
        #pragma unroll
        for (int mt = 0; mt < 4; mt++) {
            const int row = bm + wm * 64 + mt * 16 + g;
            #pragma unroll
            for (int nt = 0; nt < 4; nt++) {
                const int col = bn + wn * 32 + nt * 8 + 2 * t;
                *(__half2*)(C + (long)row * ldc + col) =
                    __floats2half2_rn(acc[mt][nt][0], acc[mt][nt][1]);
                *(__half2*)(C + (long)(row + 8) * ldc + col) =
                    __floats2half2_rn(acc[mt][nt][2], acc[mt][nt][3]);
            }
        }
        if (sym && bm != bn) {
            #pragma unroll
            for (int mt = 0; mt < 4; mt++) {
                const int row = bm + wm * 64 + mt * 16 + g;
                #pragma unroll
                for (int nt = 0; nt < 4; nt++) {
                    const int col = bn + wn * 32 + nt * 8 + 2 * t;
                    C[(long)col * ldc + row]           = __float2half(acc[mt][nt][0]);
                    C[(long)(col + 1) * ldc + row]     = __float2half(acc[mt][nt][1]);
                    C[(long)col * ldc + row + 8]       = __float2half(acc[mt][nt][2]);
                    C[(long)(col + 1) * ldc + row + 8] = __float2half(acc[mt][nt][3]);
                }
            }
        }
    } else {
        float* C = (float*)Cv + (long)batch * sC;
        #pragma unroll
        for (int mt = 0; mt < 4; mt++) {
            const int row = bm + wm * 64 + mt * 16 + g;
            #pragma unroll
            for (int nt = 0; nt < 4; nt++) {
                const int col = bn + wn * 32 + nt * 8 + 2 * t;
                *(float2*)(C + (long)row * ldc + col) =
                    make_float2(acc[mt][nt][0], acc[mt][nt][1]);
                *(float2*)(C + (long)(row + 8) * ldc + col) =
                    make_float2(acc[mt][nt][2], acc[mt][nt][3]);
            }
        }
    }
}

// ---------------------------------------------------------------------------
// Depthwise conv (kernel 3, pad 1 along last axis) + bias; fp16 in/out
// ---------------------------------------------------------------------------
__global__ __launch_bounds__(256)
void conv_bias(const __half* __restrict__ y, const float* __restrict__ wc,
               const float* __restrict__ bias, __half* __restrict__ p)
{
    long idx = (long)blockIdx.x * blockDim.x + threadIdx.x;   // 8M elems
    if (idx >= (long)BC * NB * NB) return;
    int o = (int)(idx & (NB - 1));
    int c = (int)((idx >> 20) & 3);
    float w0 = wc[c*3+0], w1 = wc[c*3+1], w2 = wc[c*3+2];
    float mid = __half2float(y[idx]);
    float lft = (o > 0)      ? __half2float(y[idx - 1]) : 0.f;
    float rgt = (o < NB - 1) ? __half2float(y[idx + 1]) : 0.f;
    p[idx] = __float2half(fmaf(lft, w0, fmaf(mid, w1, fmaf(rgt, w2, bias[c]))));
}

// ---------------------------------------------------------------------------
// RoPE + transpose: Q[bcn][s][d] from p[bc][n*128+d][s]; fp16 in/out
// ---------------------------------------------------------------------------
__global__ __launch_bounds__(256)
void rope_build(const __half* __restrict__ p, __half* __restrict__ Q)
{
    long idx = (long)blockIdx.x * blockDim.x + threadIdx.x;   // 4M
    if (idx >= (long)BCN * 64 * NB) return;
    int s   = (int)(idx & (NB - 1));
    int j   = (int)((idx >> 10) & 63);
    int bcn = (int)(idx >> 16);
    int bc = bcn >> 3, n = bcn & 7;

    const __half* src = p + ((long)bc * NB + n * HD) * NB + s;
    __half*       dst = Q + (long)bcn * (NB * HD) + (long)s * HD;

    if (j < 32) {
        float t0 = __half2float(src[(2*j + 0) * NB]);
        float t1 = __half2float(src[(2*j + 1) * NB]);
        float invf = powf(10000.f, -(float)(2*j) / (float)ROT);
        float ang = (float)s * invf;
        float cs = cosf(ang), sn = sinf(ang);
        dst[2*j + 0] = __float2half(t0 * cs - t1 * sn);
        dst[2*j + 1] = __float2half(t1 * cs + t0 * sn);
    } else {
        int d = ROT + (j - 32) * 2;
        dst[d + 0] = src[(d + 0) * NB];
        dst[d + 1] = src[(d + 1) * NB];
    }
}

// ---------------------------------------------------------------------------
// Row softmax with scale (one block per fp16 row of 1024)
// ---------------------------------------------------------------------------
__global__ __launch_bounds__(256)
void softmax_rows(__half* __restrict__ S, float scale)
{
    __half2* row2 = (__half2*)(S + (long)blockIdx.x * NB);   // 512 half2
    const int t = threadIdx.x;
    __shared__ float red[32];

    float2 a = __half22float2(row2[2*t]);
    float2 b = __half22float2(row2[2*t + 1]);
    a.x *= scale; a.y *= scale; b.x *= scale; b.y *= scale;
    float m = fmaxf(fmaxf(a.x, a.y), fmaxf(b.x, b.y));
    #pragma unroll
    for (int o = 16; o > 0; o >>= 1) m = fmaxf(m, __shfl_xor_sync(~0u, m, o));
    if ((t & 31) == 0) red[t >> 5] = m;
    __syncthreads();
    if (t < 32) {
        float x = red[t & 7];
        #pragma unroll
        for (int o = 4; o > 0; o >>= 1) x = fmaxf(x, __shfl_xor_sync(~0u, x, o));
        red[t] = x;
    }
    __syncthreads();
    m = red[0];

    a.x = __expf(a.x - m); a.y = __expf(a.y - m);
    b.x = __expf(b.x - m); b.y = __expf(b.y - m);
    float sum = a.x + a.y + b.x + b.y;
    #pragma unroll
    for (int o = 16; o > 0; o >>= 1) sum += __shfl_xor_sync(~0u, sum, o);
    __syncthreads();
    if ((t & 31) == 0) red[t >> 5] = sum;
    __syncthreads();
    if (t < 32) {
        float x = red[t & 7];
        #pragma unroll
        for (int o = 4; o > 0; o >>= 1) x += __shfl_xor_sync(~0u, x, o);
        red[t] = x;
    }
    __syncthreads();
    float inv = 1.f / red[0];
    row2[2*t]     = __floats2half2_rn(a.x * inv, a.y * inv);
    row2[2*t + 1] = __floats2half2_rn(b.x * inv, b.y * inv);
}

// ---------------------------------------------------------------------------
// Launch
// ---------------------------------------------------------------------------
extern "C" void kernel_launch(void* const* d_in, const int* in_sizes, int n_in,
                              void* d_out, int out_size)
{
    const float* x      = (const float*)d_in[0];  // (2,4,1024,1024)
    const float* w_lin  = (const float*)d_in[1];  // (4,1024,1024)
    const float* w_conv = (const float*)d_in[2];  // (4,1,1,3)
    const float* b_conv = (const float*)d_in[3];  // (4,)
    const float* w_out  = (const float*)d_in[4];  // (4,1024,1024)
    float* out = (float*)d_out;

    __half *y, *p, *q, *s, *am, *xc, *wl, *wo;
    cudaGetSymbolAddress((void**)&y,  g_y);
    cudaGetSymbolAddress((void**)&p,  g_p);
    cudaGetSymbolAddress((void**)&q,  g_q);
    cudaGetSymbolAddress((void**)&s,  g_s);
    cudaGetSymbolAddress((void**)&am, g_am);
    cudaGetSymbolAddress((void**)&xc, g_xc);
    cudaGetSymbolAddress((void**)&wl, g_wl);
    cudaGetSymbolAddress((void**)&wo, g_wo);

    cudaFuncSetAttribute(gemm_tc, cudaFuncAttributeMaxDynamicSharedMemorySize, GEMM_SMEM);

    const long MM = (long)NB * NB;          // 1048576 (elements)
    const long QS = (long)NB * HD;          // 131072

    // 0) convert GEMM inputs to fp16 (same 10-bit mantissa as tf32)
    cvt_f2h<<<(int)(BC * MM / 4 / 256), 256>>>(x, xc, (int)(BC * MM / 4));
    cvt_f2h<<<(int)(CH * MM / 4 / 256), 256>>>(w_lin, wl, (int)(CH * MM / 4));
    cvt_f2h<<<(int)(CH * MM / 4 / 256), 256>>>(w_out, wo, (int)(CH * MM / 4));

    // 1) proj GEMM: y[bc] = x[bc] @ w_lin[c]^T   (fp16 out)
    gemm_tc<<<dim3(8, 8, BC), 256, GEMM_SMEM>>>(xc, wl, y,
        NB, NB, NB, NB, MM, MM, MM, CH, 0, 1);

    // 2) depthwise conv3 + bias (fp16 p)
    conv_bias<<<(int)((BC * MM + 255) / 256), 256>>>(y, w_conv, b_conv, p);

    // 3) RoPE -> Q (== K), fp16
    rope_build<<<(int)(((long)BCN * 64 * NB + 255) / 256), 256>>>(p, q);

    // 4) scores = Q @ Q^T: symmetric -> upper-triangle tiles only + mirror
    gemm_tc<<<dim3(8, 8, BCN), 256, GEMM_SMEM>>>(q, q, s,
        HD, HD, HD, NB, QS, QS, MM, BCN, 1, 1);

    // 5) softmax rows, scale = 1/sqrt(1024), fp16 probs
    softmax_rows<<<BCN * NB, 256>>>(s, 1.0f / 32.0f);

    // 6) FUSED AV + merge-heads: am-slice[d][s] = sum_k V[k,d] * P[s,k]
    //    A = p slice (= V^T, [d][k], k contiguous, lda=NB, batch stride QS)
    //    B = S probs ([s][k], ldb=NB, batch stride MM)
    //    C = am with ldc=NB at batch stride QS -> merged layout directly.
    //    M=128 (grid.y=1), N=1024 (grid.x=8), K=1024.
    gemm_tc<<<dim3(8, 1, BCN), 256, GEMM_SMEM>>>(p, s, am,
        NB, NB, NB, NB, QS, MM, QS, BCN, 0, 1);

    // 7) out GEMM: out[bc] = am[bc] @ w_out[c]^T  (fp32 final output)
    gemm_tc<<<dim3(8, 8, BC), 256, GEMM_SMEM>>>(am, wo, out,
        NB, NB, NB, NB, MM, MM, MM, CH, 0, 0);
}